// round 2
// baseline (speedup 1.0000x reference)
#include <cuda_runtime.h>
#include <math.h>

// ---------------- problem constants (buffer sizing) ----------------
#define NNODES 5120
#define NEDGES 20000
#define BGR    128
#define MAXN   45
#define LPROT  512
#define DPROT  1280
#define TROWS  (BGR*LPROT)   // 65536

// ---------------- device scratch ----------------
__device__ float g_deg[NNODES];
__device__ float g_coef[NEDGES];
__device__ float g_xw[NNODES*256];
__device__ float g_hA[NNODES*128];
__device__ float g_h3[NNODES*256];
__device__ int   g_counts[BGR];
__device__ int   g_starts[BGR];
__device__ float g_dense[BGR*MAXN*256];
__device__ float g_fc1[BGR*MAXN*1024];
__device__ float g_hd[BGR*MAXN*128];
__device__ int   g_rowmap[TROWS];
__device__ float g_t1[TROWS*128];
__device__ float g_t[TROWS*128];
__device__ float g_tb[TROWS*128];
__device__ float g_C[BGR*LPROT*MAXN];
__device__ float g_Wpt[BGR*32*LPROT];
__device__ float g_Wcx[BGR*32*MAXN];
__device__ float g_Hc[BGR*32*MAXN];
__device__ float g_Hp[BGR*32*LPROT];
__device__ float g_cp[BGR*256];
__device__ float g_f1[BGR*1024];
__device__ float g_f2[BGR*512];

// ---------------- generic SGEMM: C[M,N] = act(gather(A)[M,K] @ B[K,N] + bias) ----------------
// rowmap (optional): A row m read from A[rowmap[m]*lda + k]
__global__ __launch_bounds__(256) void sgemm64(
    const float* __restrict__ A, int lda, const int* __restrict__ rowmap,
    const float* __restrict__ B, const float* __restrict__ bias,
    float* __restrict__ C, int M, int N, int K, int act)
{
    __shared__ float As[16][64];
    __shared__ float Bs[16][68];
    const int tid = threadIdx.y * 16 + threadIdx.x;
    const int m0 = blockIdx.y * 64;
    const int n0 = blockIdx.x * 64;
    float acc[4][4] = {};
    for (int kt = 0; kt < K; kt += 16) {
        #pragma unroll
        for (int i = tid; i < 64 * 16; i += 256) {
            int m = i >> 4, kk = i & 15;
            int gm = m0 + m, gk = kt + kk;
            float v = 0.f;
            if (gm < M && gk < K) {
                int ar = rowmap ? rowmap[gm] : gm;
                v = A[(long)ar * lda + gk];
            }
            As[kk][m] = v;
        }
        #pragma unroll
        for (int i = tid; i < 16 * 64; i += 256) {
            int kk = i >> 6, n = i & 63;
            int gk = kt + kk, gn = n0 + n;
            Bs[kk][n] = (gk < K && gn < N) ? B[(long)gk * N + gn] : 0.f;
        }
        __syncthreads();
        #pragma unroll
        for (int kk = 0; kk < 16; kk++) {
            float a[4];
            #pragma unroll
            for (int i = 0; i < 4; i++) a[i] = As[kk][threadIdx.y * 4 + i];
            float4 b4 = *(const float4*)&Bs[kk][threadIdx.x * 4];
            float bv[4] = { b4.x, b4.y, b4.z, b4.w };
            #pragma unroll
            for (int i = 0; i < 4; i++)
                #pragma unroll
                for (int j = 0; j < 4; j++) acc[i][j] += a[i] * bv[j];
        }
        __syncthreads();
    }
    #pragma unroll
    for (int i = 0; i < 4; i++) {
        int gm = m0 + threadIdx.y * 4 + i;
        if (gm >= M) continue;
        #pragma unroll
        for (int j = 0; j < 4; j++) {
            int gn = n0 + threadIdx.x * 4 + j;
            if (gn >= N) continue;
            float v = acc[i][j];
            if (bias) v += bias[gn];
            if (act == 1) v = fmaxf(v, 0.f);
            else if (act == 2) v = tanhf(v);
            C[(long)gm * N + gn] = v;
        }
    }
}

// ---------------- batched small GEMM ----------------
// C[b] = act( A[b][M,K] @ (transB ? B[b][N,K]^T : B[b][K,N]) + Add[b] )
__global__ __launch_bounds__(256) void bgemm32(
    const float* __restrict__ A, long sA, int lda,
    const float* __restrict__ B, long sB, int ldb, int transB,
    const float* __restrict__ Add, long sAdd,
    float* __restrict__ C, long sC,
    int M, int N, int K, int act)
{
    const int b = blockIdx.z;
    const float* Ab = A + (long)b * sA;
    const float* Bb = B + (long)b * sB;
    float* Cb = C + (long)b * sC;
    __shared__ float As[16][33];
    __shared__ float Bs[16][33];
    const int tid = threadIdx.y * 16 + threadIdx.x;
    const int m0 = blockIdx.y * 32, n0 = blockIdx.x * 32;
    float acc[2][2] = {};
    for (int kt = 0; kt < K; kt += 16) {
        for (int i = tid; i < 32 * 16; i += 256) {
            int m = i >> 4, kk = i & 15;
            int gm = m0 + m, gk = kt + kk;
            As[kk][m] = (gm < M && gk < K) ? Ab[(long)gm * lda + gk] : 0.f;
        }
        if (transB) {
            for (int i = tid; i < 32 * 16; i += 256) {
                int n = i >> 4, kk = i & 15;
                int gn = n0 + n, gk = kt + kk;
                Bs[kk][n] = (gn < N && gk < K) ? Bb[(long)gn * ldb + gk] : 0.f;
            }
        } else {
            for (int i = tid; i < 16 * 32; i += 256) {
                int kk = i >> 5, n = i & 31;
                int gk = kt + kk, gn = n0 + n;
                Bs[kk][n] = (gk < K && gn < N) ? Bb[(long)gk * ldb + gn] : 0.f;
            }
        }
        __syncthreads();
        #pragma unroll
        for (int kk = 0; kk < 16; kk++) {
            float a0 = As[kk][threadIdx.y * 2], a1 = As[kk][threadIdx.y * 2 + 1];
            float b0 = Bs[kk][threadIdx.x * 2], b1 = Bs[kk][threadIdx.x * 2 + 1];
            acc[0][0] += a0 * b0; acc[0][1] += a0 * b1;
            acc[1][0] += a1 * b0; acc[1][1] += a1 * b1;
        }
        __syncthreads();
    }
    for (int i = 0; i < 2; i++) {
        int gm = m0 + threadIdx.y * 2 + i;
        if (gm >= M) continue;
        for (int j = 0; j < 2; j++) {
            int gn = n0 + threadIdx.x * 2 + j;
            if (gn >= N) continue;
            float v = acc[i][j];
            if (Add) v += Add[(long)b * sAdd + (long)gm * N + gn];
            if (act == 1) v = fmaxf(v, 0.f);
            else if (act == 2) v = tanhf(v);
            Cb[(long)gm * N + gn] = v;
        }
    }
}

// ---------------- GCN helpers ----------------
__global__ void deg_init(float* deg, int n) {
    int i = blockIdx.x * blockDim.x + threadIdx.x;
    if (i < n) deg[i] = 1.0f;
}
__global__ void deg_count(const int* __restrict__ dst, float* deg, int E) {
    int e = blockIdx.x * blockDim.x + threadIdx.x;
    if (e < E) atomicAdd(&deg[dst[e]], 1.0f);
}
__global__ void edge_coef(const int* __restrict__ src, const int* __restrict__ dst,
                          const float* __restrict__ deg, float* coef, int E) {
    int e = blockIdx.x * blockDim.x + threadIdx.x;
    if (e < E) coef[e] = rsqrtf(deg[src[e]]) * rsqrtf(deg[dst[e]]);
}
__global__ void gcn_init(const float* __restrict__ xw, const float* __restrict__ deg,
                         const float* __restrict__ bias, float* out, int n, int F) {
    long i = (long)blockIdx.x * blockDim.x + threadIdx.x;
    if (i < (long)n * F) {
        int node = (int)(i / F), f = (int)(i % F);
        out[i] = xw[i] / deg[node] + bias[f];
    }
}
__global__ void gcn_scatter(const int* __restrict__ src, const int* __restrict__ dst,
                            const float* __restrict__ coef, const float* __restrict__ xw,
                            float* out, int E, int F) {
    long i = (long)blockIdx.x * blockDim.x + threadIdx.x;
    if (i < (long)E * F) {
        int e = (int)(i / F), f = (int)(i % F);
        atomicAdd(&out[(long)dst[e] * F + f], xw[(long)src[e] * F + f] * coef[e]);
    }
}
__global__ void relu_ip(float* p, long n) {
    long i = (long)blockIdx.x * blockDim.x + threadIdx.x;
    if (i < n) p[i] = fmaxf(p[i], 0.f);
}

// ---------------- to_dense_batch ----------------
__global__ void izero(int* p, int n) {
    int i = blockIdx.x * blockDim.x + threadIdx.x;
    if (i < n) p[i] = 0;
}
__global__ void fzero(float* p, long n) {
    long i = (long)blockIdx.x * blockDim.x + threadIdx.x;
    long stride = (long)gridDim.x * blockDim.x;
    for (; i < n; i += stride) p[i] = 0.f;
}
__global__ void batch_count(const int* __restrict__ batch, int* counts, int n) {
    int i = blockIdx.x * blockDim.x + threadIdx.x;
    if (i < n) atomicAdd(&counts[batch[i]], 1);
}
__global__ void scan_starts(const int* __restrict__ counts, int* starts, int B) {
    if (threadIdx.x == 0 && blockIdx.x == 0) {
        int s = 0;
        for (int i = 0; i < B; i++) { starts[i] = s; s += counts[i]; }
    }
}
__global__ void scatter_dense(const float* __restrict__ h, const int* __restrict__ batch,
                              const int* __restrict__ starts, float* dense, int n, int F) {
    long i = (long)blockIdx.x * blockDim.x + threadIdx.x;
    if (i < (long)n * F) {
        int node = (int)(i / F), f = (int)(i % F);
        int b = batch[node];
        int pos = node - starts[b];
        dense[((long)b * MAXN + pos) * F + f] = h[i];
    }
}

// ---------------- protein rowmap ----------------
__global__ void build_rowmap(const int* __restrict__ tgt, int* rowmap) {
    int r = blockIdx.x * blockDim.x + threadIdx.x;
    if (r < TROWS) rowmap[r] = tgt[r >> 9] * LPROT + (r & (LPROT - 1));
}

// ---------------- co-attention: scores, softmax, pooling ----------------
__global__ __launch_bounds__(256) void coattn(
    const float* __restrict__ Hc, const float* __restrict__ Hp,
    const float* __restrict__ whc, const float* __restrict__ whp,
    const float* __restrict__ hd, const float* __restrict__ t,
    float* __restrict__ cp)
{
    int b = blockIdx.x, tid = threadIdx.x;
    __shared__ float ac[MAXN];
    __shared__ float ap[LPROT];
    __shared__ float red[256];
    __shared__ float wc[32], wp[32];
    __shared__ float inv_p;
    if (tid < 32) { wc[tid] = whc[tid]; wp[tid] = whp[tid]; }
    __syncthreads();
    if (tid < MAXN) {
        float s = 0.f;
        #pragma unroll
        for (int k = 0; k < 32; k++) s += wc[k] * Hc[((long)b * 32 + k) * MAXN + tid];
        ac[tid] = s;
    }
    for (int l = tid; l < LPROT; l += 256) {
        float s = 0.f;
        #pragma unroll
        for (int k = 0; k < 32; k++) s += wp[k] * Hp[((long)b * 32 + k) * LPROT + l];
        ap[l] = s;
    }
    __syncthreads();
    if (tid == 0) {
        float mx = -1e30f;
        for (int s = 0; s < MAXN; s++) mx = fmaxf(mx, ac[s]);
        float sm = 0.f;
        for (int s = 0; s < MAXN; s++) { float e = expf(ac[s] - mx); ac[s] = e; sm += e; }
        float inv = 1.f / sm;
        for (int s = 0; s < MAXN; s++) ac[s] *= inv;
    }
    // softmax over ap (512)
    float lmx = -1e30f;
    for (int l = tid; l < LPROT; l += 256) lmx = fmaxf(lmx, ap[l]);
    red[tid] = lmx; __syncthreads();
    for (int o = 128; o > 0; o >>= 1) {
        if (tid < o) red[tid] = fmaxf(red[tid], red[tid + o]);
        __syncthreads();
    }
    float mx = red[0]; __syncthreads();
    float lsm = 0.f;
    for (int l = tid; l < LPROT; l += 256) { float e = expf(ap[l] - mx); ap[l] = e; lsm += e; }
    red[tid] = lsm; __syncthreads();
    for (int o = 128; o > 0; o >>= 1) {
        if (tid < o) red[tid] += red[tid + o];
        __syncthreads();
    }
    if (tid == 0) inv_p = 1.f / red[0];
    __syncthreads();
    if (tid < 128) {
        float accc = 0.f;
        for (int s = 0; s < MAXN; s++) accc += ac[s] * hd[((long)b * MAXN + s) * 128 + tid];
        cp[b * 256 + tid] = accc;
        float accp = 0.f;
        for (int l = 0; l < LPROT; l++) accp += ap[l] * t[((long)b * LPROT + l) * 128 + tid];
        cp[b * 256 + 128 + tid] = accp * inv_p;
    }
}

// ---------------- host launcher ----------------
static float* sym_f(const void* s) { void* p = nullptr; cudaGetSymbolAddress(&p, s); return (float*)p; }
static int*   sym_i(const void* s) { void* p = nullptr; cudaGetSymbolAddress(&p, s); return (int*)p; }

extern "C" void kernel_launch(void* const* d_in, const int* in_sizes, int n_in,
                              void* d_out, int out_size)
{
    const float* x      = (const float*)d_in[0];
    const int*   ei     = (const int*)d_in[1];
    const int*   tgt    = (const int*)d_in[2];
    const int*   batch  = (const int*)d_in[3];
    const float* prot   = (const float*)d_in[4];
    const float* gW1 = (const float*)d_in[5],  *gb1 = (const float*)d_in[6];
    const float* gW2 = (const float*)d_in[7],  *gb2 = (const float*)d_in[8];
    const float* gW3 = (const float*)d_in[9],  *gb3 = (const float*)d_in[10];
    const float* fc1W = (const float*)d_in[11], *fc1b = (const float*)d_in[12];
    const float* fc2W = (const float*)d_in[13], *fc2b = (const float*)d_in[14];
    const float* b1W = (const float*)d_in[15],  *b1b = (const float*)d_in[16];
    const float* b2W = (const float*)d_in[17],  *b2b = (const float*)d_in[18];
    const float* W_b = (const float*)d_in[19];
    const float* W_c = (const float*)d_in[20];
    const float* W_p = (const float*)d_in[21];
    const float* w_hc = (const float*)d_in[22], *w_hp = (const float*)d_in[23];
    const float* c1W = (const float*)d_in[24], *c1b = (const float*)d_in[25];
    const float* c2W = (const float*)d_in[26], *c2b = (const float*)d_in[27];
    const float* oW  = (const float*)d_in[28], *ob  = (const float*)d_in[29];

    const int N = in_sizes[0] / 78;
    const int E = in_sizes[1] / 2;
    const int* src = ei;
    const int* dst = ei + E;

    float* deg   = sym_f(g_deg);
    float* coef  = sym_f(g_coef);
    float* xw    = sym_f(g_xw);
    float* hA    = sym_f(g_hA);
    float* h3    = sym_f(g_h3);
    int*   counts = sym_i(g_counts);
    int*   starts = sym_i(g_starts);
    float* dense = sym_f(g_dense);
    float* fc1o  = sym_f(g_fc1);
    float* hd    = sym_f(g_hd);
    int*   rowmap = sym_i(g_rowmap);
    float* t1    = sym_f(g_t1);
    float* t     = sym_f(g_t);
    float* tb    = sym_f(g_tb);
    float* Cbuf  = sym_f(g_C);
    float* Wpt   = sym_f(g_Wpt);
    float* Wcx   = sym_f(g_Wcx);
    float* Hc    = sym_f(g_Hc);
    float* Hp    = sym_f(g_Hp);
    float* cp    = sym_f(g_cp);
    float* f1    = sym_f(g_f1);
    float* f2    = sym_f(g_f2);

    dim3 t16(16, 16);

    // ---- degrees / edge coefficients ----
    deg_init<<<(N + 255) / 256, 256>>>(deg, N);
    deg_count<<<(E + 255) / 256, 256>>>(dst, deg, E);
    edge_coef<<<(E + 255) / 256, 256>>>(src, dst, deg, coef, E);

    // ---- GCN layer 1: 78 -> 128 ----
    sgemm64<<<dim3(2, (N + 63) / 64), t16>>>(x, 78, nullptr, gW1, nullptr, xw, N, 128, 78, 0);
    gcn_init<<<((long)N * 128 + 255) / 256, 256>>>(xw, deg, gb1, hA, N, 128);
    gcn_scatter<<<((long)E * 128 + 255) / 256, 256>>>(src, dst, coef, xw, hA, E, 128);
    relu_ip<<<((long)N * 128 + 255) / 256, 256>>>(hA, (long)N * 128);

    // ---- GCN layer 2: 128 -> 128 ----
    sgemm64<<<dim3(2, (N + 63) / 64), t16>>>(hA, 128, nullptr, gW2, nullptr, xw, N, 128, 128, 0);
    gcn_init<<<((long)N * 128 + 255) / 256, 256>>>(xw, deg, gb2, hA, N, 128);
    gcn_scatter<<<((long)E * 128 + 255) / 256, 256>>>(src, dst, coef, xw, hA, E, 128);
    relu_ip<<<((long)N * 128 + 255) / 256, 256>>>(hA, (long)N * 128);

    // ---- GCN layer 3: 128 -> 256 ----
    sgemm64<<<dim3(4, (N + 63) / 64), t16>>>(hA, 128, nullptr, gW3, nullptr, xw, N, 256, 128, 0);
    gcn_init<<<((long)N * 256 + 255) / 256, 256>>>(xw, deg, gb3, h3, N, 256);
    gcn_scatter<<<((long)E * 256 + 255) / 256, 256>>>(src, dst, coef, xw, h3, E, 256);
    relu_ip<<<((long)N * 256 + 255) / 256, 256>>>(h3, (long)N * 256);

    // ---- to_dense_batch ----
    izero<<<1, 128>>>(counts, BGR);
    batch_count<<<(N + 255) / 256, 256>>>(batch, counts, N);
    scan_starts<<<1, 32>>>(counts, starts, BGR);
    fzero<<<2048, 256>>>(dense, (long)BGR * MAXN * 256);
    scatter_dense<<<((long)N * 256 + 255) / 256, 256>>>(h3, batch, starts, dense, N, 256);

    // ---- fc1 / fc2 on dense graph features ----
    const int MD = BGR * MAXN;  // 5760
    sgemm64<<<dim3(16, (MD + 63) / 64), t16>>>(dense, 256, nullptr, fc1W, fc1b, fc1o, MD, 1024, 256, 1);
    sgemm64<<<dim3(2, (MD + 63) / 64), t16>>>(fc1o, 1024, nullptr, fc2W, fc2b, hd, MD, 128, 1024, 1);

    // ---- protein branch ----
    build_rowmap<<<TROWS / 256, 256>>>(tgt, rowmap);
    sgemm64<<<dim3(2, TROWS / 64), t16>>>(prot, DPROT, rowmap, b1W, b1b, t1, TROWS, 128, DPROT, 1);
    sgemm64<<<dim3(2, TROWS / 64), t16>>>(t1, 128, nullptr, b2W, b2b, t, TROWS, 128, 128, 1);
    sgemm64<<<dim3(2, TROWS / 64), t16>>>(t, 128, nullptr, W_b, nullptr, tb, TROWS, 128, 128, 0);

    // ---- co-attention batched GEMMs ----
    // C[b] = tanh(tb[b] (512x128) @ hd[b]^T (128x45))
    bgemm32<<<dim3(2, 16, BGR), t16>>>(tb, (long)LPROT * 128, 128,
                                       hd, (long)MAXN * 128, 128, 1,
                                       nullptr, 0, Cbuf, (long)LPROT * MAXN,
                                       LPROT, MAXN, 128, 2);
    // Wpt[b] = W_p (32x128) @ t[b]^T (128x512)
    bgemm32<<<dim3(16, 1, BGR), t16>>>(W_p, 0, 128,
                                       t, (long)LPROT * 128, 128, 1,
                                       nullptr, 0, Wpt, (long)32 * LPROT,
                                       32, LPROT, 128, 0);
    // Wcx[b] = W_c (32x128) @ hd[b]^T (128x45)
    bgemm32<<<dim3(2, 1, BGR), t16>>>(W_c, 0, 128,
                                      hd, (long)MAXN * 128, 128, 1,
                                      nullptr, 0, Wcx, (long)32 * MAXN,
                                      32, MAXN, 128, 0);
    // H_c[b] = tanh(Wcx[b] + Wpt[b] (32x512) @ C[b] (512x45))
    bgemm32<<<dim3(2, 1, BGR), t16>>>(Wpt, (long)32 * LPROT, LPROT,
                                      Cbuf, (long)LPROT * MAXN, MAXN, 0,
                                      Wcx, (long)32 * MAXN, Hc, (long)32 * MAXN,
                                      32, MAXN, LPROT, 2);
    // H_p[b] = tanh(Wpt[b] + Wcx[b] (32x45) @ C[b]^T (45x512))
    bgemm32<<<dim3(16, 1, BGR), t16>>>(Wcx, (long)32 * MAXN, MAXN,
                                       Cbuf, (long)LPROT * MAXN, MAXN, 1,
                                       Wpt, (long)32 * LPROT, Hp, (long)32 * LPROT,
                                       32, LPROT, MAXN, 2);

    // ---- attention softmax + pooling -> cp [128, 256] ----
    coattn<<<BGR, 256>>>(Hc, Hp, w_hc, w_hp, hd, t, cp);

    // ---- final MLP ----
    sgemm64<<<dim3(16, 2), t16>>>(cp, 256, nullptr, c1W, c1b, f1, BGR, 1024, 256, 1);
    sgemm64<<<dim3(8, 2), t16>>>(f1, 1024, nullptr, c2W, c2b, f2, BGR, 512, 1024, 1);
    sgemm64<<<dim3(1, 2), t16>>>(f2, 512, nullptr, oW, ob, (float*)d_out, BGR, 1, 512, 0);
}

// round 4
// speedup vs baseline: 2.2825x; 2.2825x over previous
#include <cuda_runtime.h>
#include <math.h>

// ---------------- problem constants ----------------
#define NNODES 5120
#define NEDGES 20000
#define BGR    128
#define MAXN   45
#define LPROT  512
#define DPROT  1280
#define NPROT  229
#define TROWS  (BGR*LPROT)   // 65536

typedef unsigned long long u64;

// ---------------- f32x2 packed helpers (sm_103a) ----------------
__device__ __forceinline__ void ffma2(u64& d, u64 a, u64 b) {
    asm("fma.rn.f32x2 %0, %1, %2, %0;" : "+l"(d) : "l"(a), "l"(b));
}
__device__ __forceinline__ u64 packdup(float x) {
    u64 r; unsigned u = __float_as_uint(x);
    asm("mov.b64 %0, {%1, %1};" : "=l"(r) : "r"(u));
    return r;
}
__device__ __forceinline__ u64 pack2(float x, float y) {
    u64 r;
    asm("mov.b64 %0, {%1, %2};" : "=l"(r) : "r"(__float_as_uint(x)), "r"(__float_as_uint(y)));
    return r;
}
__device__ __forceinline__ float2 unpack2(u64 v) {
    unsigned lo, hi;
    asm("mov.b64 {%0, %1}, %2;" : "=r"(lo), "=r"(hi) : "l"(v));
    return make_float2(__uint_as_float(lo), __uint_as_float(hi));
}

// ---------------- device scratch ----------------
__device__ float g_deg[NNODES];
__device__ float g_coef[NEDGES];
__device__ float g_xw[NNODES*256];
__device__ float g_hA[NNODES*128];
__device__ float g_h3[NNODES*256];
__device__ int   g_counts[BGR];
__device__ int   g_starts[BGR];
__device__ float g_dense[BGR*MAXN*256];
__device__ float g_fc1[BGR*MAXN*1024];
__device__ float g_hd[BGR*MAXN*128];
__device__ int   g_rowmap[TROWS];
__device__ float g_t1[TROWS*128];
__device__ float g_t[TROWS*128];
__device__ float g_tb[TROWS*128];
__device__ float g_C[BGR*LPROT*MAXN];
__device__ float g_Wpt[BGR*32*LPROT];
__device__ float g_Wcx[BGR*32*MAXN];
__device__ float g_Hc[BGR*32*MAXN];
__device__ float g_Hp[BGR*32*LPROT];
__device__ float g_cp[BGR*256];
__device__ float g_f1[BGR*1024];
__device__ float g_f2[BGR*512];
// dedup state (1-element arrays so host-side symbol lookup gets a pointer)
__device__ int g_uflag[NPROT];
__device__ int g_uslot[NPROT];
__device__ int g_uniq[BGR];
__device__ int g_nuniq[1];
__device__ int g_Mdyn[1];
__device__ int g_bslot[BGR];

// =================================================================
// Fast SGEMM: C[M,N] = act(gather(A)[M,K] @ B[K,N] + bias)
// Requirements: M%128==0 (grid covers), N%128==0, K%16==0, lda%4==0.
// If Mdyn != null, blocks with m0 >= *Mdyn exit (Mdyn % 128 == 0).
// 256 threads, BM=128, BN=128, BK=16, 8x8 micro-tile via f32x2.
// =================================================================
__global__ __launch_bounds__(256, 2) void sgemm128(
    const float* __restrict__ A, int lda, const int* __restrict__ rowmap,
    const float* __restrict__ B, const float* __restrict__ bias,
    float* __restrict__ C, const int* __restrict__ Mdyn,
    int N, int K, int act)
{
    __shared__ float As[16][132];
    __shared__ float Bs[16][132];
    const int m0 = blockIdx.y * 128;
    if (Mdyn && m0 >= *Mdyn) return;
    const int n0 = blockIdx.x * 128;
    const int tid = threadIdx.x;
    const int tx = tid & 15, ty = tid >> 4;

    u64 acc[8][4];
    #pragma unroll
    for (int i = 0; i < 8; i++)
        #pragma unroll
        for (int j = 0; j < 4; j++) acc[i][j] = 0ULL;

    // per-thread A load descriptors (2 float4 per k-tile)
    const float* aptr[2];
    int akq[2], am[2];
    #pragma unroll
    for (int i = 0; i < 2; i++) {
        int f = tid + i * 256;        // 0..511
        am[i] = f >> 2;               // 0..127
        akq[i] = (f & 3) * 4;         // 0,4,8,12
        int row = m0 + am[i];
        int ar = rowmap ? rowmap[row] : row;
        aptr[i] = A + (long)ar * lda + akq[i];
    }

    for (int kt = 0; kt < K; kt += 16) {
        #pragma unroll
        for (int i = 0; i < 2; i++) {
            float4 v = *(const float4*)(aptr[i] + kt);
            int kq = akq[i], m = am[i];
            As[kq + 0][m] = v.x; As[kq + 1][m] = v.y;
            As[kq + 2][m] = v.z; As[kq + 3][m] = v.w;
        }
        #pragma unroll
        for (int i = 0; i < 2; i++) {
            int f = tid + i * 256;
            int kk = f >> 5, n4 = (f & 31) * 4;
            *(float4*)&Bs[kk][n4] = *(const float4*)(B + (long)(kt + kk) * N + n0 + n4);
        }
        __syncthreads();
        #pragma unroll
        for (int k = 0; k < 16; k++) {
            float4 a0 = *(const float4*)&As[k][ty * 4];
            float4 a1 = *(const float4*)&As[k][64 + ty * 4];
            float4 b0 = *(const float4*)&Bs[k][tx * 4];
            float4 b1 = *(const float4*)&Bs[k][64 + tx * 4];
            u64 bp[4] = { pack2(b0.x, b0.y), pack2(b0.z, b0.w),
                          pack2(b1.x, b1.y), pack2(b1.z, b1.w) };
            float av[8] = { a0.x, a0.y, a0.z, a0.w, a1.x, a1.y, a1.z, a1.w };
            #pragma unroll
            for (int r = 0; r < 8; r++) {
                u64 ap = packdup(av[r]);
                #pragma unroll
                for (int j = 0; j < 4; j++) ffma2(acc[r][j], ap, bp[j]);
            }
        }
        __syncthreads();
    }

    #pragma unroll
    for (int r = 0; r < 8; r++) {
        int gm = m0 + ((r < 4) ? (ty * 4 + r) : (64 + ty * 4 + r - 4));
        #pragma unroll
        for (int j = 0; j < 4; j++) {
            int gn = n0 + ((j < 2) ? (tx * 4 + j * 2) : (64 + tx * 4 + (j - 2) * 2));
            float2 v = unpack2(acc[r][j]);
            if (bias) { v.x += bias[gn]; v.y += bias[gn + 1]; }
            if (act == 1) { v.x = fmaxf(v.x, 0.f); v.y = fmaxf(v.y, 0.f); }
            else if (act == 2) { v.x = tanhf(v.x); v.y = tanhf(v.y); }
            *(float2*)&C[(long)gm * N + gn] = v;
        }
    }
}

// =================================================================
// C[b] = tanh( tb[slot(b)] (512x128) @ hd[b]^T (45x128)^T )  -> [512,45]
// grid (8, BGR), 128 threads; BM=64, N=45(pad 48), BK=32, 4x6 micro.
// =================================================================
__global__ __launch_bounds__(128) void bgemm_tbhd(
    const float* __restrict__ tb, const int* __restrict__ bslot,
    const float* __restrict__ hd, float* __restrict__ Cout)
{
    __shared__ float As[32][68];
    __shared__ float Bs[32][48];
    const int b = blockIdx.y;
    const int m0 = blockIdx.x * 64;
    const float* Ab = tb + ((long)bslot[b] * LPROT + m0) * 128;
    const float* Hb = hd + (long)b * MAXN * 128;
    const int tid = threadIdx.x;
    const int tx = tid & 7, ty = tid >> 3;

    u64 acc[4][3];
    #pragma unroll
    for (int r = 0; r < 4; r++)
        #pragma unroll
        for (int j = 0; j < 3; j++) acc[r][j] = 0ULL;

    for (int kt = 0; kt < 128; kt += 32) {
        #pragma unroll
        for (int i = 0; i < 4; i++) {
            int f = tid + i * 128;      // 0..511 float4s
            int m = f >> 3, kq = (f & 7) * 4;
            float4 v = *(const float4*)(Ab + (long)m * 128 + kt + kq);
            As[kq + 0][m] = v.x; As[kq + 1][m] = v.y;
            As[kq + 2][m] = v.z; As[kq + 3][m] = v.w;
        }
        for (int f = tid; f < MAXN * 8; f += 128) {
            int s = f >> 3, kq = (f & 7) * 4;
            float4 v = *(const float4*)(Hb + (long)s * 128 + kt + kq);
            Bs[kq + 0][s] = v.x; Bs[kq + 1][s] = v.y;
            Bs[kq + 2][s] = v.z; Bs[kq + 3][s] = v.w;
        }
        __syncthreads();
        #pragma unroll
        for (int k = 0; k < 32; k++) {
            float4 a = *(const float4*)&As[k][ty * 4];
            float2 c0 = *(const float2*)&Bs[k][tx * 6];
            float2 c1 = *(const float2*)&Bs[k][tx * 6 + 2];
            float2 c2 = *(const float2*)&Bs[k][tx * 6 + 4];
            u64 bp[3] = { pack2(c0.x, c0.y), pack2(c1.x, c1.y), pack2(c2.x, c2.y) };
            float av[4] = { a.x, a.y, a.z, a.w };
            #pragma unroll
            for (int r = 0; r < 4; r++) {
                u64 ap = packdup(av[r]);
                #pragma unroll
                for (int j = 0; j < 3; j++) ffma2(acc[r][j], ap, bp[j]);
            }
        }
        __syncthreads();
    }
    #pragma unroll
    for (int r = 0; r < 4; r++) {
        int gm = m0 + ty * 4 + r;
        #pragma unroll
        for (int j = 0; j < 3; j++) {
            int gn = tx * 6 + j * 2;
            float2 v = unpack2(acc[r][j]);
            if (gn < MAXN)     Cout[((long)b * LPROT + gm) * MAXN + gn]     = tanhf(v.x);
            if (gn + 1 < MAXN) Cout[((long)b * LPROT + gm) * MAXN + gn + 1] = tanhf(v.y);
        }
    }
}

// ---------------- generic fallback SGEMM (irregular shapes) ----------------
__global__ __launch_bounds__(256) void sgemm64(
    const float* __restrict__ A, int lda, const int* __restrict__ rowmap,
    const float* __restrict__ B, const float* __restrict__ bias,
    float* __restrict__ C, int M, int N, int K, int act)
{
    __shared__ float As[16][64];
    __shared__ float Bs[16][68];
    const int tid = threadIdx.y * 16 + threadIdx.x;
    const int m0 = blockIdx.y * 64;
    const int n0 = blockIdx.x * 64;
    float acc[4][4] = {};
    for (int kt = 0; kt < K; kt += 16) {
        #pragma unroll
        for (int i = tid; i < 64 * 16; i += 256) {
            int m = i >> 4, kk = i & 15;
            int gm = m0 + m, gk = kt + kk;
            float v = 0.f;
            if (gm < M && gk < K) {
                int ar = rowmap ? rowmap[gm] : gm;
                v = A[(long)ar * lda + gk];
            }
            As[kk][m] = v;
        }
        #pragma unroll
        for (int i = tid; i < 16 * 64; i += 256) {
            int kk = i >> 6, n = i & 63;
            int gk = kt + kk, gn = n0 + n;
            Bs[kk][n] = (gk < K && gn < N) ? B[(long)gk * N + gn] : 0.f;
        }
        __syncthreads();
        #pragma unroll
        for (int kk = 0; kk < 16; kk++) {
            float a[4];
            #pragma unroll
            for (int i = 0; i < 4; i++) a[i] = As[kk][threadIdx.y * 4 + i];
            float4 b4 = *(const float4*)&Bs[kk][threadIdx.x * 4];
            float bv[4] = { b4.x, b4.y, b4.z, b4.w };
            #pragma unroll
            for (int i = 0; i < 4; i++)
                #pragma unroll
                for (int j = 0; j < 4; j++) acc[i][j] += a[i] * bv[j];
        }
        __syncthreads();
    }
    #pragma unroll
    for (int i = 0; i < 4; i++) {
        int gm = m0 + threadIdx.y * 4 + i;
        if (gm >= M) continue;
        #pragma unroll
        for (int j = 0; j < 4; j++) {
            int gn = n0 + threadIdx.x * 4 + j;
            if (gn >= N) continue;
            float v = acc[i][j];
            if (bias) v += bias[gn];
            if (act == 1) v = fmaxf(v, 0.f);
            else if (act == 2) v = tanhf(v);
            C[(long)gm * N + gn] = v;
        }
    }
}

// ---------------- batched small GEMM ----------------
__global__ __launch_bounds__(256) void bgemm32(
    const float* __restrict__ A, long sA, int lda,
    const float* __restrict__ B, long sB, int ldb, int transB,
    const float* __restrict__ Add, long sAdd,
    float* __restrict__ C, long sC,
    int M, int N, int K, int act, const int* __restrict__ bmapB)
{
    const int b = blockIdx.z;
    const float* Ab = A + (long)b * sA;
    const float* Bb = B + (long)(bmapB ? bmapB[b] : b) * sB;
    float* Cb = C + (long)b * sC;
    __shared__ float As[16][33];
    __shared__ float Bs[16][33];
    const int tid = threadIdx.y * 16 + threadIdx.x;
    const int m0 = blockIdx.y * 32, n0 = blockIdx.x * 32;
    float acc[2][2] = {};
    for (int kt = 0; kt < K; kt += 16) {
        for (int i = tid; i < 32 * 16; i += 256) {
            int m = i >> 4, kk = i & 15;
            int gm = m0 + m, gk = kt + kk;
            As[kk][m] = (gm < M && gk < K) ? Ab[(long)gm * lda + gk] : 0.f;
        }
        if (transB) {
            for (int i = tid; i < 32 * 16; i += 256) {
                int n = i >> 4, kk = i & 15;
                int gn = n0 + n, gk = kt + kk;
                Bs[kk][n] = (gn < N && gk < K) ? Bb[(long)gn * ldb + gk] : 0.f;
            }
        } else {
            for (int i = tid; i < 16 * 32; i += 256) {
                int kk = i >> 5, n = i & 31;
                int gk = kt + kk, gn = n0 + n;
                Bs[kk][n] = (gk < K && gn < N) ? Bb[(long)gk * ldb + gn] : 0.f;
            }
        }
        __syncthreads();
        #pragma unroll
        for (int kk = 0; kk < 16; kk++) {
            float a0 = As[kk][threadIdx.y * 2], a1 = As[kk][threadIdx.y * 2 + 1];
            float b0 = Bs[kk][threadIdx.x * 2], b1 = Bs[kk][threadIdx.x * 2 + 1];
            acc[0][0] += a0 * b0; acc[0][1] += a0 * b1;
            acc[1][0] += a1 * b0; acc[1][1] += a1 * b1;
        }
        __syncthreads();
    }
    for (int i = 0; i < 2; i++) {
        int gm = m0 + threadIdx.y * 2 + i;
        if (gm >= M) continue;
        for (int j = 0; j < 2; j++) {
            int gn = n0 + threadIdx.x * 2 + j;
            if (gn >= N) continue;
            float v = acc[i][j];
            if (Add) v += Add[(long)b * sAdd + (long)gm * N + gn];
            if (act == 1) v = fmaxf(v, 0.f);
            else if (act == 2) v = tanhf(v);
            Cb[(long)gm * N + gn] = v;
        }
    }
}

// ---------------- GCN helpers ----------------
__global__ void deg_init(float* deg, int n) {
    int i = blockIdx.x * blockDim.x + threadIdx.x;
    if (i < n) deg[i] = 1.0f;
}
__global__ void deg_count(const int* __restrict__ dst, float* deg, int E) {
    int e = blockIdx.x * blockDim.x + threadIdx.x;
    if (e < E) atomicAdd(&deg[dst[e]], 1.0f);
}
__global__ void edge_coef(const int* __restrict__ src, const int* __restrict__ dst,
                          const float* __restrict__ deg, float* coef, int E) {
    int e = blockIdx.x * blockDim.x + threadIdx.x;
    if (e < E) coef[e] = rsqrtf(deg[src[e]]) * rsqrtf(deg[dst[e]]);
}
__global__ void gcn_init(const float* __restrict__ xw, const float* __restrict__ deg,
                         const float* __restrict__ bias, float* out, int n, int F) {
    long i = (long)blockIdx.x * blockDim.x + threadIdx.x;
    if (i < (long)n * F) {
        int node = (int)(i / F), f = (int)(i % F);
        out[i] = xw[i] / deg[node] + bias[f];
    }
}
__global__ void gcn_scatter(const int* __restrict__ src, const int* __restrict__ dst,
                            const float* __restrict__ coef, const float* __restrict__ xw,
                            float* out, int E, int F) {
    long i = (long)blockIdx.x * blockDim.x + threadIdx.x;
    if (i < (long)E * F) {
        int e = (int)(i / F), f = (int)(i % F);
        atomicAdd(&out[(long)dst[e] * F + f], xw[(long)src[e] * F + f] * coef[e]);
    }
}
__global__ void relu_ip(float* p, long n) {
    long i = (long)blockIdx.x * blockDim.x + threadIdx.x;
    if (i < n) p[i] = fmaxf(p[i], 0.f);
}

// ---------------- to_dense_batch ----------------
__global__ void izero(int* p, int n) {
    int i = blockIdx.x * blockDim.x + threadIdx.x;
    if (i < n) p[i] = 0;
}
__global__ void fzero(float* p, long n) {
    long i = (long)blockIdx.x * blockDim.x + threadIdx.x;
    long stride = (long)gridDim.x * blockDim.x;
    for (; i < n; i += stride) p[i] = 0.f;
}
__global__ void batch_count(const int* __restrict__ batch, int* counts, int n) {
    int i = blockIdx.x * blockDim.x + threadIdx.x;
    if (i < n) atomicAdd(&counts[batch[i]], 1);
}
__global__ void scan_starts(const int* __restrict__ counts, int* starts, int B) {
    if (threadIdx.x == 0 && blockIdx.x == 0) {
        int s = 0;
        for (int i = 0; i < B; i++) { starts[i] = s; s += counts[i]; }
    }
}
__global__ void scatter_dense(const float* __restrict__ h, const int* __restrict__ batch,
                              const int* __restrict__ starts, float* dense, int n, int F) {
    long i = (long)blockIdx.x * blockDim.x + threadIdx.x;
    if (i < (long)n * F) {
        int node = (int)(i / F), f = (int)(i % F);
        int b = batch[node];
        int pos = node - starts[b];
        dense[((long)b * MAXN + pos) * F + f] = h[i];
    }
}

// ---------------- protein dedup ----------------
__global__ void uflag_zero(int* uflag) {
    int i = blockIdx.x * blockDim.x + threadIdx.x;
    if (i < NPROT) uflag[i] = 0;
}
__global__ void uflag_set(const int* __restrict__ tgt, int* uflag) {
    int b = threadIdx.x;
    if (b < BGR) uflag[tgt[b]] = 1;
}
__global__ void uscan(const int* __restrict__ uflag, int* uslot, int* uniq,
                      int* nuniq, int* Mdyn) {
    if (threadIdx.x == 0) {
        int s = 0;
        for (int p = 0; p < NPROT; p++) {
            if (uflag[p]) { uslot[p] = s; uniq[s] = p; s++; }
            else uslot[p] = -1;
        }
        nuniq[0] = s;
        Mdyn[0] = s * LPROT;
    }
}
__global__ void bslot_build(const int* __restrict__ tgt, const int* __restrict__ uslot,
                            int* bslot) {
    int b = threadIdx.x;
    if (b < BGR) bslot[b] = uslot[tgt[b]];
}
__global__ void rowmap_build(const int* __restrict__ uniq, const int* __restrict__ nuniq,
                             int* rowmap) {
    int r = blockIdx.x * blockDim.x + threadIdx.x;
    if (r < TROWS) {
        int s = r >> 9;
        rowmap[r] = (s < nuniq[0]) ? (uniq[s] * LPROT + (r & (LPROT - 1))) : 0;
    }
}

// ---------------- co-attention softmax + pooling ----------------
__global__ __launch_bounds__(256) void coattn(
    const float* __restrict__ Hc, const float* __restrict__ Hp,
    const float* __restrict__ whc, const float* __restrict__ whp,
    const float* __restrict__ hd, const float* __restrict__ t,
    const int* __restrict__ bslot, float* __restrict__ cp)
{
    int b = blockIdx.x, tid = threadIdx.x;
    __shared__ float ac[MAXN];
    __shared__ float ap[LPROT];
    __shared__ float red[256];
    __shared__ float wc[32], wp[32];
    __shared__ float inv_p;
    if (tid < 32) { wc[tid] = whc[tid]; wp[tid] = whp[tid]; }
    __syncthreads();
    if (tid < MAXN) {
        float s = 0.f;
        #pragma unroll
        for (int k = 0; k < 32; k++) s += wc[k] * Hc[((long)b * 32 + k) * MAXN + tid];
        ac[tid] = s;
    }
    for (int l = tid; l < LPROT; l += 256) {
        float s = 0.f;
        #pragma unroll
        for (int k = 0; k < 32; k++) s += wp[k] * Hp[((long)b * 32 + k) * LPROT + l];
        ap[l] = s;
    }
    __syncthreads();
    if (tid == 0) {
        float mx = -1e30f;
        for (int s = 0; s < MAXN; s++) mx = fmaxf(mx, ac[s]);
        float sm = 0.f;
        for (int s = 0; s < MAXN; s++) { float e = expf(ac[s] - mx); ac[s] = e; sm += e; }
        float inv = 1.f / sm;
        for (int s = 0; s < MAXN; s++) ac[s] *= inv;
    }
    float lmx = -1e30f;
    for (int l = tid; l < LPROT; l += 256) lmx = fmaxf(lmx, ap[l]);
    red[tid] = lmx; __syncthreads();
    for (int o = 128; o > 0; o >>= 1) {
        if (tid < o) red[tid] = fmaxf(red[tid], red[tid + o]);
        __syncthreads();
    }
    float mx = red[0]; __syncthreads();
    float lsm = 0.f;
    for (int l = tid; l < LPROT; l += 256) { float e = expf(ap[l] - mx); ap[l] = e; lsm += e; }
    red[tid] = lsm; __syncthreads();
    for (int o = 128; o > 0; o >>= 1) {
        if (tid < o) red[tid] += red[tid + o];
        __syncthreads();
    }
    if (tid == 0) inv_p = 1.f / red[0];
    __syncthreads();
    if (tid < 128) {
        float accc = 0.f;
        for (int s = 0; s < MAXN; s++) accc += ac[s] * hd[((long)b * MAXN + s) * 128 + tid];
        cp[b * 256 + tid] = accc;
        long tbase = (long)bslot[b] * LPROT;
        float accp = 0.f;
        for (int l = 0; l < LPROT; l++) accp += ap[l] * t[(tbase + l) * 128 + tid];
        cp[b * 256 + 128 + tid] = accp * inv_p;
    }
}

// ---------------- host launcher ----------------
static float* sym_f(const void* s) { void* p = nullptr; cudaGetSymbolAddress(&p, s); return (float*)p; }
static int*   sym_i(const void* s) { void* p = nullptr; cudaGetSymbolAddress(&p, s); return (int*)p; }

extern "C" void kernel_launch(void* const* d_in, const int* in_sizes, int n_in,
                              void* d_out, int out_size)
{
    const float* x      = (const float*)d_in[0];
    const int*   ei     = (const int*)d_in[1];
    const int*   tgt    = (const int*)d_in[2];
    const int*   batch  = (const int*)d_in[3];
    const float* prot   = (const float*)d_in[4];
    const float* gW1 = (const float*)d_in[5],  *gb1 = (const float*)d_in[6];
    const float* gW2 = (const float*)d_in[7],  *gb2 = (const float*)d_in[8];
    const float* gW3 = (const float*)d_in[9],  *gb3 = (const float*)d_in[10];
    const float* fc1W = (const float*)d_in[11], *fc1b = (const float*)d_in[12];
    const float* fc2W = (const float*)d_in[13], *fc2b = (const float*)d_in[14];
    const float* b1W = (const float*)d_in[15],  *b1b = (const float*)d_in[16];
    const float* b2W = (const float*)d_in[17],  *b2b = (const float*)d_in[18];
    const float* W_b = (const float*)d_in[19];
    const float* W_c = (const float*)d_in[20];
    const float* W_p = (const float*)d_in[21];
    const float* w_hc = (const float*)d_in[22], *w_hp = (const float*)d_in[23];
    const float* c1W = (const float*)d_in[24], *c1b = (const float*)d_in[25];
    const float* c2W = (const float*)d_in[26], *c2b = (const float*)d_in[27];
    const float* oW  = (const float*)d_in[28], *ob  = (const float*)d_in[29];

    const int N = in_sizes[0] / 78;
    const int E = in_sizes[1] / 2;
    const int* src = ei;
    const int* dst = ei + E;

    float* deg   = sym_f(g_deg);
    float* coef  = sym_f(g_coef);
    float* xw    = sym_f(g_xw);
    float* hA    = sym_f(g_hA);
    float* h3    = sym_f(g_h3);
    int*   counts = sym_i(g_counts);
    int*   starts = sym_i(g_starts);
    float* dense = sym_f(g_dense);
    float* fc1o  = sym_f(g_fc1);
    float* hd    = sym_f(g_hd);
    int*   rowmap = sym_i(g_rowmap);
    float* t1    = sym_f(g_t1);
    float* t     = sym_f(g_t);
    float* tb    = sym_f(g_tb);
    float* Cbuf  = sym_f(g_C);
    float* Wpt   = sym_f(g_Wpt);
    float* Wcx   = sym_f(g_Wcx);
    float* Hc    = sym_f(g_Hc);
    float* Hp    = sym_f(g_Hp);
    float* cp    = sym_f(g_cp);
    float* f1    = sym_f(g_f1);
    float* f2    = sym_f(g_f2);
    int* uflag = sym_i(g_uflag);
    int* uslot = sym_i(g_uslot);
    int* uniq  = sym_i(g_uniq);
    int* nuniq = sym_i(g_nuniq);
    int* Mdyn  = sym_i(g_Mdyn);
    int* bslot = sym_i(g_bslot);

    dim3 t16(16, 16);

    // ---- degrees / edge coefficients ----
    deg_init<<<(N + 255) / 256, 256>>>(deg, N);
    deg_count<<<(E + 255) / 256, 256>>>(dst, deg, E);
    edge_coef<<<(E + 255) / 256, 256>>>(src, dst, deg, coef, E);

    // ---- protein dedup bookkeeping ----
    uflag_zero<<<1, 256>>>(uflag);
    uflag_set<<<1, BGR>>>(tgt, uflag);
    uscan<<<1, 32>>>(uflag, uslot, uniq, nuniq, Mdyn);
    bslot_build<<<1, BGR>>>(tgt, uslot, bslot);
    rowmap_build<<<TROWS / 256, 256>>>(uniq, nuniq, rowmap);

    // ---- GCN layer 1: 78 -> 128 (irregular K) ----
    sgemm64<<<dim3(2, (N + 63) / 64), t16>>>(x, 78, nullptr, gW1, nullptr, xw, N, 128, 78, 0);
    gcn_init<<<((long)N * 128 + 255) / 256, 256>>>(xw, deg, gb1, hA, N, 128);
    gcn_scatter<<<((long)E * 128 + 255) / 256, 256>>>(src, dst, coef, xw, hA, E, 128);
    relu_ip<<<((long)N * 128 + 255) / 256, 256>>>(hA, (long)N * 128);

    // ---- GCN layer 2: 128 -> 128 ----
    sgemm128<<<dim3(1, N / 128), 256>>>(hA, 128, nullptr, gW2, nullptr, xw, nullptr, 128, 128, 0);
    gcn_init<<<((long)N * 128 + 255) / 256, 256>>>(xw, deg, gb2, hA, N, 128);
    gcn_scatter<<<((long)E * 128 + 255) / 256, 256>>>(src, dst, coef, xw, hA, E, 128);
    relu_ip<<<((long)N * 128 + 255) / 256, 256>>>(hA, (long)N * 128);

    // ---- GCN layer 3: 128 -> 256 ----
    sgemm128<<<dim3(2, N / 128), 256>>>(hA, 128, nullptr, gW3, nullptr, xw, nullptr, 256, 128, 0);
    gcn_init<<<((long)N * 256 + 255) / 256, 256>>>(xw, deg, gb3, h3, N, 256);
    gcn_scatter<<<((long)E * 256 + 255) / 256, 256>>>(src, dst, coef, xw, h3, E, 256);
    relu_ip<<<((long)N * 256 + 255) / 256, 256>>>(h3, (long)N * 256);

    // ---- to_dense_batch ----
    izero<<<1, 128>>>(counts, BGR);
    batch_count<<<(N + 255) / 256, 256>>>(batch, counts, N);
    scan_starts<<<1, 32>>>(counts, starts, BGR);
    fzero<<<2048, 256>>>(dense, (long)BGR * MAXN * 256);
    scatter_dense<<<((long)N * 256 + 255) / 256, 256>>>(h3, batch, starts, dense, N, 256);

    // ---- fc1 / fc2 on dense graph features ----
    const int MD = BGR * MAXN;  // 5760 = 45*128
    sgemm128<<<dim3(8, MD / 128), 256>>>(dense, 256, nullptr, fc1W, fc1b, fc1o, nullptr, 1024, 256, 1);
    sgemm128<<<dim3(1, MD / 128), 256>>>(fc1o, 1024, nullptr, fc2W, fc2b, hd, nullptr, 128, 1024, 1);

    // ---- protein branch (dedup: M = nuniq*512, dynamic) ----
    sgemm128<<<dim3(1, TROWS / 128), 256>>>(prot, DPROT, rowmap, b1W, b1b, t1, Mdyn, 128, DPROT, 1);
    sgemm128<<<dim3(1, TROWS / 128), 256>>>(t1, 128, nullptr, b2W, b2b, t, Mdyn, 128, 128, 1);
    sgemm128<<<dim3(1, TROWS / 128), 256>>>(t, 128, nullptr, W_b, nullptr, tb, Mdyn, 128, 128, 0);

    // ---- co-attention ----
    // C[b] = tanh(tb[slot(b)] @ hd[b]^T)  [512,45]
    bgemm_tbhd<<<dim3(LPROT / 64, BGR), 128>>>(tb, bslot, hd, Cbuf);
    // Wpt[b] = W_p @ t[slot(b)]^T  [32,512]
    bgemm32<<<dim3(16, 1, BGR), t16>>>(W_p, 0, 128,
                                       t, (long)LPROT * 128, 128, 1,
                                       nullptr, 0, Wpt, (long)32 * LPROT,
                                       32, LPROT, 128, 0, bslot);
    // Wcx[b] = W_c @ hd[b]^T  [32,45]
    bgemm32<<<dim3(2, 1, BGR), t16>>>(W_c, 0, 128,
                                      hd, (long)MAXN * 128, 128, 1,
                                      nullptr, 0, Wcx, (long)32 * MAXN,
                                      32, MAXN, 128, 0, nullptr);
    // H_c[b] = tanh(Wcx[b] + Wpt[b] @ C[b])  [32,45]
    bgemm32<<<dim3(2, 1, BGR), t16>>>(Wpt, (long)32 * LPROT, LPROT,
                                      Cbuf, (long)LPROT * MAXN, MAXN, 0,
                                      Wcx, (long)32 * MAXN, Hc, (long)32 * MAXN,
                                      32, MAXN, LPROT, 2, nullptr);
    // H_p[b] = tanh(Wpt[b] + Wcx[b] @ C[b]^T)  [32,512]
    bgemm32<<<dim3(16, 1, BGR), t16>>>(Wcx, (long)32 * MAXN, MAXN,
                                       Cbuf, (long)LPROT * MAXN, MAXN, 1,
                                       Wpt, (long)32 * LPROT, Hp, (long)32 * LPROT,
                                       32, LPROT, MAXN, 2, nullptr);

    // ---- attention softmax + pooling -> cp [128, 256] ----
    coattn<<<BGR, 256>>>(Hc, Hp, w_hc, w_hp, hd, t, bslot, cp);

    // ---- final MLP ----
    sgemm128<<<dim3(8, 1), 256>>>(cp, 256, nullptr, c1W, c1b, f1, nullptr, 1024, 256, 1);
    sgemm128<<<dim3(4, 1), 256>>>(f1, 1024, nullptr, c2W, c2b, f2, nullptr, 512, 1024, 1);
    sgemm64<<<dim3(1, 2), t16>>>(f2, 512, nullptr, oW, ob, (float*)d_out, BGR, 1, 512, 0);
}

// round 5
// speedup vs baseline: 2.6396x; 1.1565x over previous
#include <cuda_runtime.h>
#include <math.h>

// ---------------- problem constants ----------------
#define NNODES 5120
#define NEDGES 20000
#define BGR    128
#define MAXN   45
#define LPROT  512
#define DPROT  1280
#define NPROT  229
#define TROWS  (BGR*LPROT)   // 65536

typedef unsigned long long u64;

// ---------------- f32x2 packed helpers (sm_103a) ----------------
__device__ __forceinline__ void ffma2(u64& d, u64 a, u64 b) {
    asm("fma.rn.f32x2 %0, %1, %2, %0;" : "+l"(d) : "l"(a), "l"(b));
}
__device__ __forceinline__ u64 packdup(float x) {
    u64 r; unsigned u = __float_as_uint(x);
    asm("mov.b64 %0, {%1, %1};" : "=l"(r) : "r"(u));
    return r;
}
__device__ __forceinline__ u64 pack2(float x, float y) {
    u64 r;
    asm("mov.b64 %0, {%1, %2};" : "=l"(r) : "r"(__float_as_uint(x)), "r"(__float_as_uint(y)));
    return r;
}
__device__ __forceinline__ float2 unpack2(u64 v) {
    unsigned lo, hi;
    asm("mov.b64 {%0, %1}, %2;" : "=r"(lo), "=r"(hi) : "l"(v));
    return make_float2(__uint_as_float(lo), __uint_as_float(hi));
}

// ---------------- device scratch ----------------
__device__ float g_deg[NNODES];
__device__ float g_coef[NEDGES];
__device__ float g_xw[NNODES*256];
__device__ float g_hA[NNODES*128];
__device__ float g_hB[NNODES*128];
__device__ float g_h3[NNODES*256];
__device__ int   g_counts[BGR];
__device__ int   g_starts[BGR];
__device__ float g_dense[BGR*MAXN*256];
__device__ float g_fc1[BGR*MAXN*1024];
__device__ float g_hd[BGR*MAXN*128];
__device__ int   g_rowmap[TROWS];
__device__ float g_t1[TROWS*128];
__device__ float g_t[TROWS*128];
__device__ float g_tb[TROWS*128];
__device__ float g_C[BGR*LPROT*MAXN];
__device__ float g_Wpt[BGR*32*LPROT];
__device__ float g_Wcx[BGR*32*MAXN];
__device__ float g_Hc[BGR*32*MAXN];
__device__ float g_Hp[BGR*32*LPROT];
__device__ float g_cp[BGR*256];
__device__ float g_f1[BGR*1024];
__device__ float g_f2[BGR*512];
__device__ int g_Mdyn[1];
__device__ int g_bslot[BGR];

// =================================================================
// Fast SGEMM: C[M,N] = act(relu?(gather(A))[M,K] @ B[K,N] + bias)
// Optional dual output: C2[m,n] = acc/degv[m] + bias2[n]  (GCN init)
// M%128==0 (grid covers), N%128==0, K%16==0.
// =================================================================
__global__ __launch_bounds__(256, 2) void sgemm128(
    const float* __restrict__ A, int lda, const int* __restrict__ rowmap,
    const float* __restrict__ B, const float* __restrict__ bias,
    float* __restrict__ C, const int* __restrict__ Mdyn,
    int N, int K, int act, int preRelu,
    float* __restrict__ C2, const float* __restrict__ degv,
    const float* __restrict__ bias2)
{
    __shared__ float As[16][132];
    __shared__ float Bs[16][132];
    const int m0 = blockIdx.y * 128;
    if (Mdyn && m0 >= *Mdyn) return;
    const int n0 = blockIdx.x * 128;
    const int tid = threadIdx.x;
    const int tx = tid & 15, ty = tid >> 4;

    u64 acc[8][4];
    #pragma unroll
    for (int i = 0; i < 8; i++)
        #pragma unroll
        for (int j = 0; j < 4; j++) acc[i][j] = 0ULL;

    const float* aptr[2];
    int akq[2], am[2];
    #pragma unroll
    for (int i = 0; i < 2; i++) {
        int f = tid + i * 256;
        am[i] = f >> 2;
        akq[i] = (f & 3) * 4;
        int row = m0 + am[i];
        int ar = rowmap ? rowmap[row] : row;
        aptr[i] = A + (long)ar * lda + akq[i];
    }

    for (int kt = 0; kt < K; kt += 16) {
        #pragma unroll
        for (int i = 0; i < 2; i++) {
            float4 v = *(const float4*)(aptr[i] + kt);
            if (preRelu) {
                v.x = fmaxf(v.x, 0.f); v.y = fmaxf(v.y, 0.f);
                v.z = fmaxf(v.z, 0.f); v.w = fmaxf(v.w, 0.f);
            }
            int kq = akq[i], m = am[i];
            As[kq + 0][m] = v.x; As[kq + 1][m] = v.y;
            As[kq + 2][m] = v.z; As[kq + 3][m] = v.w;
        }
        #pragma unroll
        for (int i = 0; i < 2; i++) {
            int f = tid + i * 256;
            int kk = f >> 5, n4 = (f & 31) * 4;
            *(float4*)&Bs[kk][n4] = *(const float4*)(B + (long)(kt + kk) * N + n0 + n4);
        }
        __syncthreads();
        #pragma unroll
        for (int k = 0; k < 16; k++) {
            float4 a0 = *(const float4*)&As[k][ty * 4];
            float4 a1 = *(const float4*)&As[k][64 + ty * 4];
            float4 b0 = *(const float4*)&Bs[k][tx * 4];
            float4 b1 = *(const float4*)&Bs[k][64 + tx * 4];
            u64 bp[4] = { pack2(b0.x, b0.y), pack2(b0.z, b0.w),
                          pack2(b1.x, b1.y), pack2(b1.z, b1.w) };
            float av[8] = { a0.x, a0.y, a0.z, a0.w, a1.x, a1.y, a1.z, a1.w };
            #pragma unroll
            for (int r = 0; r < 8; r++) {
                u64 ap = packdup(av[r]);
                #pragma unroll
                for (int j = 0; j < 4; j++) ffma2(acc[r][j], ap, bp[j]);
            }
        }
        __syncthreads();
    }

    #pragma unroll
    for (int r = 0; r < 8; r++) {
        int gm = m0 + ((r < 4) ? (ty * 4 + r) : (64 + ty * 4 + r - 4));
        #pragma unroll
        for (int j = 0; j < 4; j++) {
            int gn = n0 + ((j < 2) ? (tx * 4 + j * 2) : (64 + tx * 4 + (j - 2) * 2));
            float2 v = unpack2(acc[r][j]);
            if (C2) {
                float dg = degv[gm];
                float2 w = make_float2(v.x / dg + bias2[gn], v.y / dg + bias2[gn + 1]);
                *(float2*)&C2[(long)gm * N + gn] = w;
            }
            if (bias) { v.x += bias[gn]; v.y += bias[gn + 1]; }
            if (act == 1) { v.x = fmaxf(v.x, 0.f); v.y = fmaxf(v.y, 0.f); }
            else if (act == 2) { v.x = tanhf(v.x); v.y = tanhf(v.y); }
            *(float2*)&C[(long)gm * N + gn] = v;
        }
    }
}

// =================================================================
// C[b] = tanh( tb[slot(b)] (512x128) @ hd[b]^T )  -> [512,45]
// =================================================================
__global__ __launch_bounds__(128) void bgemm_tbhd(
    const float* __restrict__ tb, const int* __restrict__ bslot,
    const float* __restrict__ hd, float* __restrict__ Cout)
{
    __shared__ float As[32][68];
    __shared__ float Bs[32][48];
    const int b = blockIdx.y;
    const int m0 = blockIdx.x * 64;
    const float* Ab = tb + ((long)bslot[b] * LPROT + m0) * 128;
    const float* Hb = hd + (long)b * MAXN * 128;
    const int tid = threadIdx.x;
    const int tx = tid & 7, ty = tid >> 3;

    u64 acc[4][3];
    #pragma unroll
    for (int r = 0; r < 4; r++)
        #pragma unroll
        for (int j = 0; j < 3; j++) acc[r][j] = 0ULL;

    for (int kt = 0; kt < 128; kt += 32) {
        #pragma unroll
        for (int i = 0; i < 4; i++) {
            int f = tid + i * 128;
            int m = f >> 3, kq = (f & 7) * 4;
            float4 v = *(const float4*)(Ab + (long)m * 128 + kt + kq);
            As[kq + 0][m] = v.x; As[kq + 1][m] = v.y;
            As[kq + 2][m] = v.z; As[kq + 3][m] = v.w;
        }
        for (int f = tid; f < MAXN * 8; f += 128) {
            int s = f >> 3, kq = (f & 7) * 4;
            float4 v = *(const float4*)(Hb + (long)s * 128 + kt + kq);
            Bs[kq + 0][s] = v.x; Bs[kq + 1][s] = v.y;
            Bs[kq + 2][s] = v.z; Bs[kq + 3][s] = v.w;
        }
        __syncthreads();
        #pragma unroll
        for (int k = 0; k < 32; k++) {
            float4 a = *(const float4*)&As[k][ty * 4];
            float2 c0 = *(const float2*)&Bs[k][tx * 6];
            float2 c1 = *(const float2*)&Bs[k][tx * 6 + 2];
            float2 c2 = *(const float2*)&Bs[k][tx * 6 + 4];
            u64 bp[3] = { pack2(c0.x, c0.y), pack2(c1.x, c1.y), pack2(c2.x, c2.y) };
            float av[4] = { a.x, a.y, a.z, a.w };
            #pragma unroll
            for (int r = 0; r < 4; r++) {
                u64 ap = packdup(av[r]);
                #pragma unroll
                for (int j = 0; j < 3; j++) ffma2(acc[r][j], ap, bp[j]);
            }
        }
        __syncthreads();
    }
    #pragma unroll
    for (int r = 0; r < 4; r++) {
        int gm = m0 + ty * 4 + r;
        #pragma unroll
        for (int j = 0; j < 3; j++) {
            int gn = tx * 6 + j * 2;
            float2 v = unpack2(acc[r][j]);
            if (gn < MAXN)     Cout[((long)b * LPROT + gm) * MAXN + gn]     = tanhf(v.x);
            if (gn + 1 < MAXN) Cout[((long)b * LPROT + gm) * MAXN + gn + 1] = tanhf(v.y);
        }
    }
}

// ---------------- generic fallback SGEMM ----------------
__global__ __launch_bounds__(256) void sgemm64(
    const float* __restrict__ A, int lda, const int* __restrict__ rowmap,
    const float* __restrict__ B, const float* __restrict__ bias,
    float* __restrict__ C, int M, int N, int K, int act,
    float* __restrict__ C2, const float* __restrict__ degv,
    const float* __restrict__ bias2)
{
    __shared__ float As[16][64];
    __shared__ float Bs[16][68];
    const int tid = threadIdx.y * 16 + threadIdx.x;
    const int m0 = blockIdx.y * 64;
    const int n0 = blockIdx.x * 64;
    float acc[4][4] = {};
    for (int kt = 0; kt < K; kt += 16) {
        #pragma unroll
        for (int i = tid; i < 64 * 16; i += 256) {
            int m = i >> 4, kk = i & 15;
            int gm = m0 + m, gk = kt + kk;
            float v = 0.f;
            if (gm < M && gk < K) {
                int ar = rowmap ? rowmap[gm] : gm;
                v = A[(long)ar * lda + gk];
            }
            As[kk][m] = v;
        }
        #pragma unroll
        for (int i = tid; i < 16 * 64; i += 256) {
            int kk = i >> 6, n = i & 63;
            int gk = kt + kk, gn = n0 + n;
            Bs[kk][n] = (gk < K && gn < N) ? B[(long)gk * N + gn] : 0.f;
        }
        __syncthreads();
        #pragma unroll
        for (int kk = 0; kk < 16; kk++) {
            float a[4];
            #pragma unroll
            for (int i = 0; i < 4; i++) a[i] = As[kk][threadIdx.y * 4 + i];
            float4 b4 = *(const float4*)&Bs[kk][threadIdx.x * 4];
            float bv[4] = { b4.x, b4.y, b4.z, b4.w };
            #pragma unroll
            for (int i = 0; i < 4; i++)
                #pragma unroll
                for (int j = 0; j < 4; j++) acc[i][j] += a[i] * bv[j];
        }
        __syncthreads();
    }
    #pragma unroll
    for (int i = 0; i < 4; i++) {
        int gm = m0 + threadIdx.y * 4 + i;
        if (gm >= M) continue;
        #pragma unroll
        for (int j = 0; j < 4; j++) {
            int gn = n0 + threadIdx.x * 4 + j;
            if (gn >= N) continue;
            float v = acc[i][j];
            if (C2) C2[(long)gm * N + gn] = v / degv[gm] + bias2[gn];
            if (bias) v += bias[gn];
            if (act == 1) v = fmaxf(v, 0.f);
            else if (act == 2) v = tanhf(v);
            C[(long)gm * N + gn] = v;
        }
    }
}

// ---------------- batched small GEMM ----------------
__global__ __launch_bounds__(256) void bgemm32(
    const float* __restrict__ A, long sA, int lda,
    const float* __restrict__ B, long sB, int ldb, int transB,
    const float* __restrict__ Add, long sAdd,
    float* __restrict__ C, long sC,
    int M, int N, int K, int act, const int* __restrict__ bmapB)
{
    const int b = blockIdx.z;
    const float* Ab = A + (long)b * sA;
    const float* Bb = B + (long)(bmapB ? bmapB[b] : b) * sB;
    float* Cb = C + (long)b * sC;
    __shared__ float As[16][33];
    __shared__ float Bs[16][33];
    const int tid = threadIdx.y * 16 + threadIdx.x;
    const int m0 = blockIdx.y * 32, n0 = blockIdx.x * 32;
    float acc[2][2] = {};
    for (int kt = 0; kt < K; kt += 16) {
        for (int i = tid; i < 32 * 16; i += 256) {
            int m = i >> 4, kk = i & 15;
            int gm = m0 + m, gk = kt + kk;
            As[kk][m] = (gm < M && gk < K) ? Ab[(long)gm * lda + gk] : 0.f;
        }
        if (transB) {
            for (int i = tid; i < 32 * 16; i += 256) {
                int n = i >> 4, kk = i & 15;
                int gn = n0 + n, gk = kt + kk;
                Bs[kk][n] = (gn < N && gk < K) ? Bb[(long)gn * ldb + gk] : 0.f;
            }
        } else {
            for (int i = tid; i < 16 * 32; i += 256) {
                int kk = i >> 5, n = i & 31;
                int gk = kt + kk, gn = n0 + n;
                Bs[kk][n] = (gk < K && gn < N) ? Bb[(long)gk * ldb + gn] : 0.f;
            }
        }
        __syncthreads();
        #pragma unroll
        for (int kk = 0; kk < 16; kk++) {
            float a0 = As[kk][threadIdx.y * 2], a1 = As[kk][threadIdx.y * 2 + 1];
            float b0 = Bs[kk][threadIdx.x * 2], b1 = Bs[kk][threadIdx.x * 2 + 1];
            acc[0][0] += a0 * b0; acc[0][1] += a0 * b1;
            acc[1][0] += a1 * b0; acc[1][1] += a1 * b1;
        }
        __syncthreads();
    }
    for (int i = 0; i < 2; i++) {
        int gm = m0 + threadIdx.y * 2 + i;
        if (gm >= M) continue;
        for (int j = 0; j < 2; j++) {
            int gn = n0 + threadIdx.x * 2 + j;
            if (gn >= N) continue;
            float v = acc[i][j];
            if (Add) v += Add[(long)b * sAdd + (long)gm * N + gn];
            if (act == 1) v = fmaxf(v, 0.f);
            else if (act == 2) v = tanhf(v);
            Cb[(long)gm * N + gn] = v;
        }
    }
}

// ---------------- GCN helpers ----------------
__global__ void deg_init(float* deg, int n) {
    int i = blockIdx.x * blockDim.x + threadIdx.x;
    if (i < n) deg[i] = 1.0f;
}
__global__ void deg_count(const int* __restrict__ dst, float* deg, int E) {
    int e = blockIdx.x * blockDim.x + threadIdx.x;
    if (e < E) atomicAdd(&deg[dst[e]], 1.0f);
}
__global__ void edge_coef(const int* __restrict__ src, const int* __restrict__ dst,
                          const float* __restrict__ deg, float* coef, int E) {
    int e = blockIdx.x * blockDim.x + threadIdx.x;
    if (e < E) coef[e] = rsqrtf(deg[src[e]]) * rsqrtf(deg[dst[e]]);
}
__global__ void gcn_scatter(const int* __restrict__ src, const int* __restrict__ dst,
                            const float* __restrict__ coef, const float* __restrict__ xw,
                            float* out, int E, int F) {
    long i = (long)blockIdx.x * blockDim.x + threadIdx.x;
    if (i < (long)E * F) {
        int e = (int)(i / F), f = (int)(i % F);
        atomicAdd(&out[(long)dst[e] * F + f], xw[(long)src[e] * F + f] * coef[e]);
    }
}

// ---------------- to_dense_batch (fused) ----------------
__global__ void counts_starts(const int* __restrict__ batch, int n,
                              int* counts, int* starts) {
    __shared__ int c[BGR];
    int tid = threadIdx.x;
    if (tid < BGR) c[tid] = 0;
    __syncthreads();
    for (int i = tid; i < n; i += blockDim.x) atomicAdd(&c[batch[i]], 1);
    __syncthreads();
    if (tid == 0) {
        int s = 0;
        for (int b = 0; b < BGR; b++) { starts[b] = s; counts[b] = c[b]; s += c[b]; }
    }
}
// dense[b, pos, f] = pos < counts[b] ? relu(h3[starts[b]+pos, f]) : 0   (float4 lanes)
__global__ void dense_build(const float* __restrict__ h3,
                            const int* __restrict__ counts,
                            const int* __restrict__ starts,
                            float* __restrict__ dense) {
    int i = blockIdx.x * blockDim.x + threadIdx.x;
    if (i >= BGR * MAXN * 64) return;
    int b = i / (MAXN * 64);
    int rem = i - b * (MAXN * 64);
    int pos = rem >> 6, f4 = rem & 63;
    float4 v = make_float4(0.f, 0.f, 0.f, 0.f);
    if (pos < counts[b]) {
        v = ((const float4*)(h3 + (long)(starts[b] + pos) * 256))[f4];
        v.x = fmaxf(v.x, 0.f); v.y = fmaxf(v.y, 0.f);
        v.z = fmaxf(v.z, 0.f); v.w = fmaxf(v.w, 0.f);
    }
    ((float4*)dense)[i] = v;
}

// ---------------- protein dedup (fused, one block) ----------------
__global__ void dedup_fused(const int* __restrict__ tgt,
                            int* bslot, int* rowmap, int* Mdyn) {
    __shared__ int flag[NPROT];
    __shared__ int slot[NPROT];
    __shared__ int uniq[BGR];
    __shared__ int nu_s;
    int tid = threadIdx.x;
    if (tid < NPROT) flag[tid] = 0;
    __syncthreads();
    if (tid < BGR) flag[tgt[tid]] = 1;
    __syncthreads();
    if (tid == 0) {
        int s = 0;
        for (int p = 0; p < NPROT; p++) {
            if (flag[p]) { slot[p] = s; uniq[s] = p; s++; }
            else slot[p] = -1;
        }
        nu_s = s;
        Mdyn[0] = s * LPROT;
    }
    __syncthreads();
    if (tid < BGR) bslot[tid] = slot[tgt[tid]];
    int nu = nu_s;
    for (int r = tid; r < TROWS; r += blockDim.x) {
        int s = r >> 9;
        rowmap[r] = (s < nu) ? (uniq[s] * LPROT + (r & (LPROT - 1))) : 0;
    }
}

// ---------------- co-attention softmax + pooling ----------------
__global__ __launch_bounds__(256) void coattn(
    const float* __restrict__ Hc, const float* __restrict__ Hp,
    const float* __restrict__ whc, const float* __restrict__ whp,
    const float* __restrict__ hd, const float* __restrict__ t,
    const int* __restrict__ bslot, float* __restrict__ cp)
{
    int b = blockIdx.x, tid = threadIdx.x;
    __shared__ float ac[MAXN];
    __shared__ float ap[LPROT];
    __shared__ float red[256];
    __shared__ float wc[32], wp[32];
    __shared__ float inv_p;
    if (tid < 32) { wc[tid] = whc[tid]; wp[tid] = whp[tid]; }
    __syncthreads();
    if (tid < MAXN) {
        float s = 0.f;
        #pragma unroll
        for (int k = 0; k < 32; k++) s += wc[k] * Hc[((long)b * 32 + k) * MAXN + tid];
        ac[tid] = s;
    }
    for (int l = tid; l < LPROT; l += 256) {
        float s = 0.f;
        #pragma unroll
        for (int k = 0; k < 32; k++) s += wp[k] * Hp[((long)b * 32 + k) * LPROT + l];
        ap[l] = s;
    }
    __syncthreads();
    if (tid == 0) {
        float mx = -1e30f;
        for (int s = 0; s < MAXN; s++) mx = fmaxf(mx, ac[s]);
        float sm = 0.f;
        for (int s = 0; s < MAXN; s++) { float e = expf(ac[s] - mx); ac[s] = e; sm += e; }
        float inv = 1.f / sm;
        for (int s = 0; s < MAXN; s++) ac[s] *= inv;
    }
    float lmx = -1e30f;
    for (int l = tid; l < LPROT; l += 256) lmx = fmaxf(lmx, ap[l]);
    red[tid] = lmx; __syncthreads();
    for (int o = 128; o > 0; o >>= 1) {
        if (tid < o) red[tid] = fmaxf(red[tid], red[tid + o]);
        __syncthreads();
    }
    float mx = red[0]; __syncthreads();
    float lsm = 0.f;
    for (int l = tid; l < LPROT; l += 256) { float e = expf(ap[l] - mx); ap[l] = e; lsm += e; }
    red[tid] = lsm; __syncthreads();
    for (int o = 128; o > 0; o >>= 1) {
        if (tid < o) red[tid] += red[tid + o];
        __syncthreads();
    }
    if (tid == 0) inv_p = 1.f / red[0];
    __syncthreads();
    if (tid < 128) {
        float accc = 0.f;
        for (int s = 0; s < MAXN; s++) accc += ac[s] * hd[((long)b * MAXN + s) * 128 + tid];
        cp[b * 256 + tid] = accc;
        long tbase = (long)bslot[b] * LPROT;
        float accp = 0.f;
        for (int l = 0; l < LPROT; l++) accp += ap[l] * t[(tbase + l) * 128 + tid];
        cp[b * 256 + 128 + tid] = accp * inv_p;
    }
}

// ---------------- host launcher ----------------
static float* sym_f(const void* s) { void* p = nullptr; cudaGetSymbolAddress(&p, s); return (float*)p; }
static int*   sym_i(const void* s) { void* p = nullptr; cudaGetSymbolAddress(&p, s); return (int*)p; }

extern "C" void kernel_launch(void* const* d_in, const int* in_sizes, int n_in,
                              void* d_out, int out_size)
{
    const float* x      = (const float*)d_in[0];
    const int*   ei     = (const int*)d_in[1];
    const int*   tgt    = (const int*)d_in[2];
    const int*   batch  = (const int*)d_in[3];
    const float* prot   = (const float*)d_in[4];
    const float* gW1 = (const float*)d_in[5],  *gb1 = (const float*)d_in[6];
    const float* gW2 = (const float*)d_in[7],  *gb2 = (const float*)d_in[8];
    const float* gW3 = (const float*)d_in[9],  *gb3 = (const float*)d_in[10];
    const float* fc1W = (const float*)d_in[11], *fc1b = (const float*)d_in[12];
    const float* fc2W = (const float*)d_in[13], *fc2b = (const float*)d_in[14];
    const float* b1W = (const float*)d_in[15],  *b1b = (const float*)d_in[16];
    const float* b2W = (const float*)d_in[17],  *b2b = (const float*)d_in[18];
    const float* W_b = (const float*)d_in[19];
    const float* W_c = (const float*)d_in[20];
    const float* W_p = (const float*)d_in[21];
    const float* w_hc = (const float*)d_in[22], *w_hp = (const float*)d_in[23];
    const float* c1W = (const float*)d_in[24], *c1b = (const float*)d_in[25];
    const float* c2W = (const float*)d_in[26], *c2b = (const float*)d_in[27];
    const float* oW  = (const float*)d_in[28], *ob  = (const float*)d_in[29];

    const int N = in_sizes[0] / 78;
    const int E = in_sizes[1] / 2;
    const int* src = ei;
    const int* dst = ei + E;

    float* deg   = sym_f(g_deg);
    float* coef  = sym_f(g_coef);
    float* xw    = sym_f(g_xw);
    float* hA    = sym_f(g_hA);
    float* hB    = sym_f(g_hB);
    float* h3    = sym_f(g_h3);
    int*   counts = sym_i(g_counts);
    int*   starts = sym_i(g_starts);
    float* dense = sym_f(g_dense);
    float* fc1o  = sym_f(g_fc1);
    float* hd    = sym_f(g_hd);
    int*   rowmap = sym_i(g_rowmap);
    float* t1    = sym_f(g_t1);
    float* t     = sym_f(g_t);
    float* tb    = sym_f(g_tb);
    float* Cbuf  = sym_f(g_C);
    float* Wpt   = sym_f(g_Wpt);
    float* Wcx   = sym_f(g_Wcx);
    float* Hc    = sym_f(g_Hc);
    float* Hp    = sym_f(g_Hp);
    float* cp    = sym_f(g_cp);
    float* f1    = sym_f(g_f1);
    float* f2    = sym_f(g_f2);
    int* Mdyn  = sym_i(g_Mdyn);
    int* bslot = sym_i(g_bslot);

    // one-time stream/event setup (created on first — uncaptured — call)
    static cudaStream_t sB = 0;
    static cudaEvent_t evF = 0, evJ = 0;
    static int tried = 0;
    if (!tried) {
        tried = 1;
        if (cudaStreamCreateWithFlags(&sB, cudaStreamNonBlocking) != cudaSuccess) sB = 0;
        if (sB) {
            if (cudaEventCreateWithFlags(&evF, cudaEventDisableTiming) != cudaSuccess ||
                cudaEventCreateWithFlags(&evJ, cudaEventDisableTiming) != cudaSuccess) {
                sB = 0;
            }
        }
    }
    const bool fork = (sB != 0);
    cudaStream_t PS = fork ? sB : (cudaStream_t)0;

    dim3 t16(16, 16);

    // ---- dedup bookkeeping (needed by protein branch) ----
    dedup_fused<<<1, 256>>>(tgt, bslot, rowmap, Mdyn);

    // ---- fork: protein branch on PS ----
    if (fork) { cudaEventRecord(evF, 0); cudaStreamWaitEvent(sB, evF, 0); }
    sgemm128<<<dim3(1, TROWS / 128), 256, 0, PS>>>(prot, DPROT, rowmap, b1W, b1b, t1, Mdyn, 128, DPROT, 1, 0, nullptr, nullptr, nullptr);
    sgemm128<<<dim3(1, TROWS / 128), 256, 0, PS>>>(t1, 128, nullptr, b2W, b2b, t, Mdyn, 128, 128, 1, 0, nullptr, nullptr, nullptr);
    sgemm128<<<dim3(1, TROWS / 128), 256, 0, PS>>>(t, 128, nullptr, W_b, nullptr, tb, Mdyn, 128, 128, 0, 0, nullptr, nullptr, nullptr);
    // Wpt[b] = W_p @ t[slot(b)]^T  [32,512]
    bgemm32<<<dim3(16, 1, BGR), t16, 0, PS>>>(W_p, 0, 128,
                                              t, (long)LPROT * 128, 128, 1,
                                              nullptr, 0, Wpt, (long)32 * LPROT,
                                              32, LPROT, 128, 0, bslot);
    if (fork) cudaEventRecord(evJ, sB);

    // ---- main branch: degrees / GCN / dense / fc ----
    deg_init<<<(N + 255) / 256, 256>>>(deg, N);
    deg_count<<<(E + 255) / 256, 256>>>(dst, deg, E);
    edge_coef<<<(E + 255) / 256, 256>>>(src, dst, deg, coef, E);

    // GCN layer 1: 78 -> 128 (dual output: xw raw, hA = xw/deg + b)
    sgemm64<<<dim3(2, (N + 63) / 64), t16>>>(x, 78, nullptr, gW1, nullptr, xw, N, 128, 78, 0, hA, deg, gb1);
    gcn_scatter<<<((long)E * 128 + 255) / 256, 256>>>(src, dst, coef, xw, hA, E, 128);

    // GCN layer 2: 128 -> 128 (preRelu on hA; dual output into hB)
    sgemm128<<<dim3(1, N / 128), 256>>>(hA, 128, nullptr, gW2, nullptr, xw, nullptr, 128, 128, 0, 1, hB, deg, gb2);
    gcn_scatter<<<((long)E * 128 + 255) / 256, 256>>>(src, dst, coef, xw, hB, E, 128);

    // GCN layer 3: 128 -> 256 (preRelu on hB; dual output into h3)
    sgemm128<<<dim3(2, N / 128), 256>>>(hB, 128, nullptr, gW3, nullptr, xw, nullptr, 256, 128, 0, 1, h3, deg, gb3);
    gcn_scatter<<<((long)E * 256 + 255) / 256, 256>>>(src, dst, coef, xw, h3, E, 256);

    // to_dense_batch (relu fused into gather)
    counts_starts<<<1, 256>>>(batch, N, counts, starts);
    dense_build<<<(BGR * MAXN * 64 + 255) / 256, 256>>>(h3, counts, starts, dense);

    // fc1 / fc2
    const int MD = BGR * MAXN;  // 5760
    sgemm128<<<dim3(8, MD / 128), 256>>>(dense, 256, nullptr, fc1W, fc1b, fc1o, nullptr, 1024, 256, 1, 0, nullptr, nullptr, nullptr);
    sgemm128<<<dim3(1, MD / 128), 256>>>(fc1o, 1024, nullptr, fc2W, fc2b, hd, nullptr, 128, 1024, 1, 0, nullptr, nullptr, nullptr);

    // Wcx[b] = W_c @ hd[b]^T  [32,45]
    bgemm32<<<dim3(2, 1, BGR), t16>>>(W_c, 0, 128,
                                      hd, (long)MAXN * 128, 128, 1,
                                      nullptr, 0, Wcx, (long)32 * MAXN,
                                      32, MAXN, 128, 0, nullptr);

    // ---- join ----
    if (fork) cudaStreamWaitEvent(0, evJ, 0);

    // C[b] = tanh(tb[slot(b)] @ hd[b]^T)  [512,45]
    bgemm_tbhd<<<dim3(LPROT / 64, BGR), 128>>>(tb, bslot, hd, Cbuf);
    // H_c[b] = tanh(Wcx[b] + Wpt[b] @ C[b])  [32,45]
    bgemm32<<<dim3(2, 1, BGR), t16>>>(Wpt, (long)32 * LPROT, LPROT,
                                      Cbuf, (long)LPROT * MAXN, MAXN, 0,
                                      Wcx, (long)32 * MAXN, Hc, (long)32 * MAXN,
                                      32, MAXN, LPROT, 2, nullptr);
    // H_p[b] = tanh(Wpt[b] + Wcx[b] @ C[b]^T)  [32,512]
    bgemm32<<<dim3(16, 1, BGR), t16>>>(Wcx, (long)32 * MAXN, MAXN,
                                       Cbuf, (long)LPROT * MAXN, MAXN, 1,
                                       Wpt, (long)32 * LPROT, Hp, (long)32 * LPROT,
                                       32, LPROT, MAXN, 2, nullptr);

    // attention softmax + pooling -> cp [128, 256]
    coattn<<<BGR, 256>>>(Hc, Hp, w_hc, w_hp, hd, t, bslot, cp);

    // final MLP
    sgemm128<<<dim3(8, 1), 256>>>(cp, 256, nullptr, c1W, c1b, f1, nullptr, 1024, 256, 1, 0, nullptr, nullptr, nullptr);
    sgemm128<<<dim3(4, 1), 256>>>(f1, 1024, nullptr, c2W, c2b, f2, nullptr, 512, 1024, 1, 0, nullptr, nullptr, nullptr);
    sgemm64<<<dim3(1, 2), t16>>>(f2, 512, nullptr, oW, ob, (float*)d_out, BGR, 1, 512, 0, nullptr, nullptr, nullptr);
}

// round 6
// speedup vs baseline: 2.7968x; 1.0596x over previous
#include <cuda_runtime.h>
#include <math.h>

// ---------------- problem constants ----------------
#define NNODES 5120
#define NEDGES 20000
#define BGR    128
#define MAXN   45
#define LPROT  512
#define DPROT  1280
#define NPROT  229
#define TROWS  (BGR*LPROT)   // 65536

typedef unsigned long long u64;

// ---------------- f32x2 packed helpers (sm_103a) ----------------
__device__ __forceinline__ void ffma2(u64& d, u64 a, u64 b) {
    asm("fma.rn.f32x2 %0, %1, %2, %0;" : "+l"(d) : "l"(a), "l"(b));
}
__device__ __forceinline__ u64 packdup(float x) {
    u64 r; unsigned u = __float_as_uint(x);
    asm("mov.b64 %0, {%1, %1};" : "=l"(r) : "r"(u));
    return r;
}
__device__ __forceinline__ u64 pack2(float x, float y) {
    u64 r;
    asm("mov.b64 %0, {%1, %2};" : "=l"(r) : "r"(__float_as_uint(x)), "r"(__float_as_uint(y)));
    return r;
}
__device__ __forceinline__ float2 unpack2(u64 v) {
    unsigned lo, hi;
    asm("mov.b64 {%0, %1}, %2;" : "=r"(lo), "=r"(hi) : "l"(v));
    return make_float2(__uint_as_float(lo), __uint_as_float(hi));
}

// ---------------- device scratch ----------------
__device__ float g_deg[NNODES];
__device__ float g_coef[NEDGES];
__device__ float g_xw[NNODES*256];
__device__ float g_hA[NNODES*128];
__device__ float g_hB[NNODES*128];
__device__ float g_h3[NNODES*256];
__device__ int   g_counts[BGR];
__device__ int   g_starts[BGR];
__device__ float g_dense[BGR*MAXN*256];
__device__ float g_fc1[BGR*MAXN*1024];
__device__ float g_hd[BGR*MAXN*128];
__device__ int   g_rowmap[TROWS];
__device__ float g_t1[TROWS*128];
__device__ float g_t[TROWS*128];
__device__ float g_tbw[(long)TROWS*256];   // [tb | WptT | pad]
__device__ float g_wcomb[128*256];
__device__ float g_cp[BGR*256];
__device__ float g_f1[BGR*1024];
__device__ float g_f2[BGR*512];
__device__ int g_Mdyn[1];
__device__ int g_bslot[BGR];

// =================================================================
// Fast SGEMM with register prefetch:
// C = act(relu?(gather(A)) @ B + bias); optional C2 = acc/deg + bias2
// =================================================================
__global__ __launch_bounds__(256, 2) void sgemm128(
    const float* __restrict__ A, int lda, const int* __restrict__ rowmap,
    const float* __restrict__ B, const float* __restrict__ bias,
    float* __restrict__ C, const int* __restrict__ Mdyn,
    int N, int K, int act, int preRelu,
    float* __restrict__ C2, const float* __restrict__ degv,
    const float* __restrict__ bias2)
{
    __shared__ float As[16][132];
    __shared__ float Bs[16][132];
    const int m0 = blockIdx.y * 128;
    if (Mdyn && m0 >= *Mdyn) return;
    const int n0 = blockIdx.x * 128;
    const int tid = threadIdx.x;
    const int tx = tid & 15, ty = tid >> 4;

    u64 acc[8][4];
    #pragma unroll
    for (int i = 0; i < 8; i++)
        #pragma unroll
        for (int j = 0; j < 4; j++) acc[i][j] = 0ULL;

    const float* aptr[2];
    int akq[2], am[2];
    #pragma unroll
    for (int i = 0; i < 2; i++) {
        int f = tid + i * 256;
        am[i] = f >> 2;
        akq[i] = (f & 3) * 4;
        int row = m0 + am[i];
        int ar = rowmap ? rowmap[row] : row;
        aptr[i] = A + (long)ar * lda + akq[i];
    }
    const float* bptr[2];
    int bkk[2];
    const int bn4 = (tid & 31) * 4;
    #pragma unroll
    for (int i = 0; i < 2; i++) {
        bkk[i] = (tid >> 5) + i * 8;
        bptr[i] = B + (long)bkk[i] * N + n0 + bn4;
    }

    float4 pa[2], pb[2];
    #pragma unroll
    for (int i = 0; i < 2; i++) { pa[i] = *(const float4*)(aptr[i]); pb[i] = *(const float4*)(bptr[i]); }

    for (int kt = 0; kt < K; kt += 16) {
        #pragma unroll
        for (int i = 0; i < 2; i++) {
            float4 v = pa[i];
            if (preRelu) {
                v.x = fmaxf(v.x, 0.f); v.y = fmaxf(v.y, 0.f);
                v.z = fmaxf(v.z, 0.f); v.w = fmaxf(v.w, 0.f);
            }
            int kq = akq[i], m = am[i];
            As[kq + 0][m] = v.x; As[kq + 1][m] = v.y;
            As[kq + 2][m] = v.z; As[kq + 3][m] = v.w;
        }
        #pragma unroll
        for (int i = 0; i < 2; i++) *(float4*)&Bs[bkk[i]][bn4] = pb[i];
        __syncthreads();
        if (kt + 16 < K) {
            #pragma unroll
            for (int i = 0; i < 2; i++) {
                pa[i] = *(const float4*)(aptr[i] + kt + 16);
                pb[i] = *(const float4*)(bptr[i] + (long)(kt + 16) * N);
            }
        }
        #pragma unroll
        for (int k = 0; k < 16; k++) {
            float4 a0 = *(const float4*)&As[k][ty * 4];
            float4 a1 = *(const float4*)&As[k][64 + ty * 4];
            float4 b0 = *(const float4*)&Bs[k][tx * 4];
            float4 b1 = *(const float4*)&Bs[k][64 + tx * 4];
            u64 bp[4] = { pack2(b0.x, b0.y), pack2(b0.z, b0.w),
                          pack2(b1.x, b1.y), pack2(b1.z, b1.w) };
            float av[8] = { a0.x, a0.y, a0.z, a0.w, a1.x, a1.y, a1.z, a1.w };
            #pragma unroll
            for (int r = 0; r < 8; r++) {
                u64 ap = packdup(av[r]);
                #pragma unroll
                for (int j = 0; j < 4; j++) ffma2(acc[r][j], ap, bp[j]);
            }
        }
        __syncthreads();
    }

    #pragma unroll
    for (int r = 0; r < 8; r++) {
        int gm = m0 + ((r < 4) ? (ty * 4 + r) : (64 + ty * 4 + r - 4));
        #pragma unroll
        for (int j = 0; j < 4; j++) {
            int gn = n0 + ((j < 2) ? (tx * 4 + j * 2) : (64 + tx * 4 + (j - 2) * 2));
            float2 v = unpack2(acc[r][j]);
            if (C2) {
                float dg = degv[gm];
                float2 w = make_float2(v.x / dg + bias2[gn], v.y / dg + bias2[gn + 1]);
                *(float2*)&C2[(long)gm * N + gn] = w;
            }
            if (bias) { v.x += bias[gn]; v.y += bias[gn + 1]; }
            if (act == 1) { v.x = fmaxf(v.x, 0.f); v.y = fmaxf(v.y, 0.f); }
            else if (act == 2) { v.x = tanhf(v.x); v.y = tanhf(v.y); }
            *(float2*)&C[(long)gm * N + gn] = v;
        }
    }
}

// ---------------- generic fallback SGEMM (GCN layer 1, K=78) ----------------
__global__ __launch_bounds__(256) void sgemm64(
    const float* __restrict__ A, int lda,
    const float* __restrict__ B, float* __restrict__ C,
    int M, int N, int K,
    float* __restrict__ C2, const float* __restrict__ degv,
    const float* __restrict__ bias2)
{
    __shared__ float As[16][64];
    __shared__ float Bs[16][68];
    const int tid = threadIdx.y * 16 + threadIdx.x;
    const int m0 = blockIdx.y * 64;
    const int n0 = blockIdx.x * 64;
    float acc[4][4] = {};
    for (int kt = 0; kt < K; kt += 16) {
        #pragma unroll
        for (int i = tid; i < 64 * 16; i += 256) {
            int m = i >> 4, kk = i & 15;
            int gm = m0 + m, gk = kt + kk;
            float v = 0.f;
            if (gm < M && gk < K) v = A[(long)gm * lda + gk];
            As[kk][m] = v;
        }
        #pragma unroll
        for (int i = tid; i < 16 * 64; i += 256) {
            int kk = i >> 6, n = i & 63;
            int gk = kt + kk, gn = n0 + n;
            Bs[kk][n] = (gk < K && gn < N) ? B[(long)gk * N + gn] : 0.f;
        }
        __syncthreads();
        #pragma unroll
        for (int kk = 0; kk < 16; kk++) {
            float a[4];
            #pragma unroll
            for (int i = 0; i < 4; i++) a[i] = As[kk][threadIdx.y * 4 + i];
            float4 b4 = *(const float4*)&Bs[kk][threadIdx.x * 4];
            float bv[4] = { b4.x, b4.y, b4.z, b4.w };
            #pragma unroll
            for (int i = 0; i < 4; i++)
                #pragma unroll
                for (int j = 0; j < 4; j++) acc[i][j] += a[i] * bv[j];
        }
        __syncthreads();
    }
    #pragma unroll
    for (int i = 0; i < 4; i++) {
        int gm = m0 + threadIdx.y * 4 + i;
        if (gm >= M) continue;
        #pragma unroll
        for (int j = 0; j < 4; j++) {
            int gn = n0 + threadIdx.x * 4 + j;
            if (gn >= N) continue;
            float v = acc[i][j];
            if (C2) C2[(long)gm * N + gn] = v / degv[gm] + bias2[gn];
            C[(long)gm * N + gn] = v;
        }
    }
}

// ---------------- graph prep (deg + coef fused, one block) ----------------
__global__ void graph_prep(const int* __restrict__ src, const int* __restrict__ dst,
                           int n, int E, float* deg, float* coef) {
    __shared__ float sdeg[NNODES];
    int tid = threadIdx.x;
    for (int i = tid; i < n; i += blockDim.x) sdeg[i] = 1.0f;
    __syncthreads();
    for (int e = tid; e < E; e += blockDim.x) atomicAdd(&sdeg[dst[e]], 1.0f);
    __syncthreads();
    for (int i = tid; i < n; i += blockDim.x) deg[i] = sdeg[i];
    for (int e = tid; e < E; e += blockDim.x)
        coef[e] = rsqrtf(sdeg[src[e]]) * rsqrtf(sdeg[dst[e]]);
}

__global__ void gcn_scatter(const int* __restrict__ src, const int* __restrict__ dst,
                            const float* __restrict__ coef, const float* __restrict__ xw,
                            float* out, int E, int F) {
    long i = (long)blockIdx.x * blockDim.x + threadIdx.x;
    if (i < (long)E * F) {
        int e = (int)(i / F), f = (int)(i % F);
        atomicAdd(&out[(long)dst[e] * F + f], xw[(long)src[e] * F + f] * coef[e]);
    }
}

// ---------------- to_dense_batch ----------------
__global__ void counts_starts(const int* __restrict__ batch, int n,
                              int* counts, int* starts) {
    __shared__ int c[BGR];
    int tid = threadIdx.x;
    if (tid < BGR) c[tid] = 0;
    __syncthreads();
    for (int i = tid; i < n; i += blockDim.x) atomicAdd(&c[batch[i]], 1);
    __syncthreads();
    if (tid == 0) {
        int s = 0;
        for (int b = 0; b < BGR; b++) { starts[b] = s; counts[b] = c[b]; s += c[b]; }
    }
}
__global__ void dense_build(const float* __restrict__ h3,
                            const int* __restrict__ counts,
                            const int* __restrict__ starts,
                            float* __restrict__ dense) {
    int i = blockIdx.x * blockDim.x + threadIdx.x;
    if (i >= BGR * MAXN * 64) return;
    int b = i / (MAXN * 64);
    int rem = i - b * (MAXN * 64);
    int pos = rem >> 6, f4 = rem & 63;
    float4 v = make_float4(0.f, 0.f, 0.f, 0.f);
    if (pos < counts[b]) {
        v = ((const float4*)(h3 + (long)(starts[b] + pos) * 256))[f4];
        v.x = fmaxf(v.x, 0.f); v.y = fmaxf(v.y, 0.f);
        v.z = fmaxf(v.z, 0.f); v.w = fmaxf(v.w, 0.f);
    }
    ((float4*)dense)[i] = v;
}

// ---------------- protein dedup (fused, one block) ----------------
__global__ void dedup_fused(const int* __restrict__ tgt,
                            int* bslot, int* rowmap, int* Mdyn) {
    __shared__ int flag[NPROT];
    __shared__ int slot[NPROT];
    __shared__ int uniq[BGR];
    __shared__ int nu_s;
    int tid = threadIdx.x;
    if (tid < NPROT) flag[tid] = 0;
    __syncthreads();
    if (tid < BGR) flag[tgt[tid]] = 1;
    __syncthreads();
    if (tid == 0) {
        int s = 0;
        for (int p = 0; p < NPROT; p++) {
            if (flag[p]) { slot[p] = s; uniq[s] = p; s++; }
            else slot[p] = -1;
        }
        nu_s = s;
        Mdyn[0] = s * LPROT;
    }
    __syncthreads();
    if (tid < BGR) bslot[tid] = slot[tgt[tid]];
    int nu = nu_s;
    for (int r = tid; r < TROWS; r += blockDim.x) {
        int s = r >> 9;
        rowmap[r] = (s < nu) ? (uniq[s] * LPROT + (r & (LPROT - 1))) : 0;
    }
}

// ---------------- Wcomb = [W_b | W_p^T | 0]  [128,256] ----------------
__global__ void wcomb_build(const float* __restrict__ Wb, const float* __restrict__ Wp,
                            float* __restrict__ Wc) {
    int i = blockIdx.x * 256 + threadIdx.x;
    if (i >= 128 * 256) return;
    int k = i >> 8, n = i & 255;
    float v = 0.f;
    if (n < 128) v = Wb[k * 128 + n];
    else if (n < 160) v = Wp[(n - 128) * 128 + k];
    Wc[i] = v;
}

// =================================================================
// FUSED CO-ATTENTION: one block per batch, 256 threads, ~80KB smem.
// Computes Wcx, C (chunked), Hc, Hp, both softmaxes, and pooling.
// tbw rows: [tb(128) | WptT(32) | pad(96)]
// =================================================================
#define PHD 132
#define OFF_HD   0
#define OFF_WCX  (OFF_HD + 45*PHD)          // 5940
#define OFF_C    (OFF_WCX + 32*48)          // +1536
#define OFF_TB   (OFF_C + 64*48)            // +3072
#define OFF_AP   (OFF_TB + 64*PHD)          // +8448
#define OFF_AC   (OFF_AP + 512)
#define OFF_RED  (OFF_AC + 48)
#define OFF_WC   (OFF_RED + 256)
#define OFF_WP   (OFF_WC + 32)
#define OFF_SCAL (OFF_WP + 32)
#define SM_FLOATS (OFF_SCAL + 4)

__global__ __launch_bounds__(256) void coattn_fused(
    const float* __restrict__ tbw, const float* __restrict__ t,
    const float* __restrict__ hd, const float* __restrict__ Wc_g,
    const float* __restrict__ whc, const float* __restrict__ whp,
    const int* __restrict__ bslot, float* __restrict__ cp)
{
    extern __shared__ float sm[];
    float* s_hd  = sm + OFF_HD;
    float* s_wcx = sm + OFF_WCX;
    float* s_C   = sm + OFF_C;
    float* s_tb  = sm + OFF_TB;
    float* s_ap  = sm + OFF_AP;
    float* s_ac  = sm + OFF_AC;
    float* s_red = sm + OFF_RED;
    float* s_wc  = sm + OFF_WC;
    float* s_wp  = sm + OFF_WP;
    float* s_scal= sm + OFF_SCAL;

    const int b = blockIdx.x;
    const int tid = threadIdx.x;
    const long base = (long)bslot[b] * LPROT;
    const float* hd_b = hd + (long)b * MAXN * 128;

    // ---- init: load hd, weights, zero ac ----
    for (int idx = tid; idx < MAXN * 32; idx += 256) {
        int s = idx >> 5, v4 = (idx & 31) * 4;
        *(float4*)&s_hd[s * PHD + v4] = *(const float4*)&hd_b[s * 128 + v4];
    }
    if (tid < 32) { s_wc[tid] = whc[tid]; s_wp[tid] = whp[tid]; }
    if (tid < 48) s_ac[tid] = 0.f;
    __syncthreads();

    // ---- Wcx[k][s] = dot(W_c[k], hd[s]) ----
    for (int idx = tid; idx < 32 * MAXN; idx += 256) {
        int k = idx / MAXN, s = idx - k * MAXN;
        float acc = 0.f;
        #pragma unroll
        for (int kk = 0; kk < 32; kk++) {
            float4 a = *(const float4*)&Wc_g[k * 128 + kk * 4];
            float4 h4 = *(const float4*)&s_hd[s * PHD + kk * 4];
            acc += a.x * h4.x + a.y * h4.y + a.z * h4.z + a.w * h4.w;
        }
        s_wcx[k * 48 + s] = acc;
    }

    // persistent Hc accumulators (2k x 3s tile per thread, tid<240)
    const int kt2 = (tid / 15) * 2;
    const int st3 = (tid % 15) * 3;
    float hc00 = 0.f, hc01 = 0.f, hc02 = 0.f, hc10 = 0.f, hc11 = 0.f, hc12 = 0.f;

    // ---- chunk loop over l (8 chunks of 64) ----
    for (int cc = 0; cc < 8; cc++) {
        const int lbase = cc * 64;
        __syncthreads();   // previous chunk consumers done
        // load tb chunk
        for (int idx = tid; idx < 64 * 32; idx += 256) {
            int l = idx >> 5, v4 = (idx & 31) * 4;
            *(float4*)&s_tb[l * PHD + v4] =
                *(const float4*)&tbw[(base + lbase + l) * 256 + v4];
        }
        __syncthreads();
        // C[l][s] = tanh(dot(tb[l], hd[s]))   (4l x 3s tiles, tid<240)
        if (tid < 240) {
            int lt = (tid / 15) * 4;
            float ca[4][3] = {};
            #pragma unroll 8
            for (int kk = 0; kk < 32; kk++) {
                float4 a0 = *(const float4*)&s_tb[(lt + 0) * PHD + kk * 4];
                float4 a1 = *(const float4*)&s_tb[(lt + 1) * PHD + kk * 4];
                float4 a2 = *(const float4*)&s_tb[(lt + 2) * PHD + kk * 4];
                float4 a3 = *(const float4*)&s_tb[(lt + 3) * PHD + kk * 4];
                float4 h0 = *(const float4*)&s_hd[(st3 + 0) * PHD + kk * 4];
                float4 h1 = *(const float4*)&s_hd[(st3 + 1) * PHD + kk * 4];
                float4 h2 = *(const float4*)&s_hd[(st3 + 2) * PHD + kk * 4];
                ca[0][0] += a0.x*h0.x + a0.y*h0.y + a0.z*h0.z + a0.w*h0.w;
                ca[0][1] += a0.x*h1.x + a0.y*h1.y + a0.z*h1.z + a0.w*h1.w;
                ca[0][2] += a0.x*h2.x + a0.y*h2.y + a0.z*h2.z + a0.w*h2.w;
                ca[1][0] += a1.x*h0.x + a1.y*h0.y + a1.z*h0.z + a1.w*h0.w;
                ca[1][1] += a1.x*h1.x + a1.y*h1.y + a1.z*h1.z + a1.w*h1.w;
                ca[1][2] += a1.x*h2.x + a1.y*h2.y + a1.z*h2.z + a1.w*h2.w;
                ca[2][0] += a2.x*h0.x + a2.y*h0.y + a2.z*h0.z + a2.w*h0.w;
                ca[2][1] += a2.x*h1.x + a2.y*h1.y + a2.z*h1.z + a2.w*h1.w;
                ca[2][2] += a2.x*h2.x + a2.y*h2.y + a2.z*h2.z + a2.w*h2.w;
                ca[3][0] += a3.x*h0.x + a3.y*h0.y + a3.z*h0.z + a3.w*h0.w;
                ca[3][1] += a3.x*h1.x + a3.y*h1.y + a3.z*h1.z + a3.w*h1.w;
                ca[3][2] += a3.x*h2.x + a3.y*h2.y + a3.z*h2.z + a3.w*h2.w;
            }
            #pragma unroll
            for (int i = 0; i < 4; i++)
                #pragma unroll
                for (int j = 0; j < 3; j++)
                    s_C[(lt + i) * 48 + st3 + j] = tanhf(ca[i][j]);
        }
        __syncthreads();
        // Hc accumulate: hc[k][s] += sum_l WptT[l][k] * C[l][s]
        if (tid < 240) {
            for (int l = 0; l < 64; l++) {
                const float* wrow = &tbw[(base + lbase + l) * 256 + 128];
                float w0 = wrow[kt2], w1 = wrow[kt2 + 1];
                float c0 = s_C[l * 48 + st3];
                float c1 = s_C[l * 48 + st3 + 1];
                float c2 = s_C[l * 48 + st3 + 2];
                hc00 += w0 * c0; hc01 += w0 * c1; hc02 += w0 * c2;
                hc10 += w1 * c0; hc11 += w1 * c1; hc12 += w1 * c2;
            }
        }
        // Hp scores: ap[l] = sum_k w_hp[k]*tanh(WptT[l][k] + sum_s Wcx[k][s]*C[l][s])
        {
            int l = tid >> 2, q = tid & 3;
            float cl[45];
            #pragma unroll
            for (int s = 0; s < 45; s++) cl[s] = s_C[l * 48 + s];
            const float* wrow = &tbw[(base + lbase + l) * 256 + 128];
            float part = 0.f;
            #pragma unroll
            for (int i = 0; i < 8; i++) {
                int k = q * 8 + i;
                float v = wrow[k];
                const float* wx = &s_wcx[k * 48];
                #pragma unroll
                for (int s = 0; s < 45; s++) v += wx[s] * cl[s];
                part += s_wp[k] * tanhf(v);
            }
            part += __shfl_down_sync(0xffffffffu, part, 2);
            part += __shfl_down_sync(0xffffffffu, part, 1);
            if (q == 0) s_ap[lbase + l] = part;
        }
    }
    __syncthreads();

    // ---- ac scores: atomic partials of sum_k w_hc[k]*tanh(Wcx + Hc) ----
    if (tid < 240) {
        float h;
        h = tanhf(s_wcx[kt2 * 48 + st3] + hc00);       atomicAdd(&s_ac[st3],     s_wc[kt2] * h);
        h = tanhf(s_wcx[kt2 * 48 + st3 + 1] + hc01);   atomicAdd(&s_ac[st3 + 1], s_wc[kt2] * h);
        h = tanhf(s_wcx[kt2 * 48 + st3 + 2] + hc02);   atomicAdd(&s_ac[st3 + 2], s_wc[kt2] * h);
        h = tanhf(s_wcx[(kt2+1) * 48 + st3] + hc10);     atomicAdd(&s_ac[st3],     s_wc[kt2+1] * h);
        h = tanhf(s_wcx[(kt2+1) * 48 + st3 + 1] + hc11); atomicAdd(&s_ac[st3 + 1], s_wc[kt2+1] * h);
        h = tanhf(s_wcx[(kt2+1) * 48 + st3 + 2] + hc12); atomicAdd(&s_ac[st3 + 2], s_wc[kt2+1] * h);
    }
    __syncthreads();

    // ---- softmax over ap (512), all threads ----
    float m1 = fmaxf(s_ap[tid], s_ap[tid + 256]);
    s_red[tid] = m1; __syncthreads();
    for (int o = 128; o > 0; o >>= 1) {
        if (tid < o) s_red[tid] = fmaxf(s_red[tid], s_red[tid + o]);
        __syncthreads();
    }
    float mx = s_red[0]; __syncthreads();
    float e1 = expf(s_ap[tid] - mx), e2 = expf(s_ap[tid + 256] - mx);
    s_ap[tid] = e1; s_ap[tid + 256] = e2;
    s_red[tid] = e1 + e2; __syncthreads();
    for (int o = 128; o > 0; o >>= 1) {
        if (tid < o) s_red[tid] += s_red[tid + o];
        __syncthreads();
    }
    if (tid == 0) s_scal[0] = 1.f / s_red[0];
    // ---- softmax over ac (45), thread 0 serial ----
    if (tid == 0) {
        float amx = -1e30f;
        for (int s = 0; s < MAXN; s++) amx = fmaxf(amx, s_ac[s]);
        float sum = 0.f;
        for (int s = 0; s < MAXN; s++) { float e = expf(s_ac[s] - amx); s_ac[s] = e; sum += e; }
        float inv = 1.f / sum;
        for (int s = 0; s < MAXN; s++) s_ac[s] *= inv;
    }
    __syncthreads();

    // ---- pooling ----
    {
        int h = tid >> 7, m = tid & 127;
        float accp = 0.f;
        int l0 = h * 256;
        for (int l = 0; l < 256; l++)
            accp += s_ap[l0 + l] * t[(base + l0 + l) * 128 + m];
        s_red[tid] = accp;
        __syncthreads();
        if (h == 0) {
            float accc = 0.f;
            #pragma unroll
            for (int s = 0; s < MAXN; s++) accc += s_ac[s] * s_hd[s * PHD + m];
            cp[b * 256 + m] = accc;
            cp[b * 256 + 128 + m] = (s_red[m] + s_red[128 + m]) * s_scal[0];
        }
    }
}

// ---------------- final output: out[b] = f2[b] . oW + ob ----------------
__global__ void out_kernel(const float* __restrict__ f2, const float* __restrict__ oW,
                           const float* __restrict__ ob, float* __restrict__ out) {
    int b = threadIdx.x;
    if (b < BGR) {
        float s = 0.f;
        for (int j = 0; j < 512; j += 4) {
            float4 a = *(const float4*)&f2[b * 512 + j];
            float4 w = *(const float4*)&oW[j];
            s += a.x * w.x + a.y * w.y + a.z * w.z + a.w * w.w;
        }
        out[b] = s + ob[0];
    }
}

// ---------------- host launcher ----------------
static float* sym_f(const void* s) { void* p = nullptr; cudaGetSymbolAddress(&p, s); return (float*)p; }
static int*   sym_i(const void* s) { void* p = nullptr; cudaGetSymbolAddress(&p, s); return (int*)p; }

extern "C" void kernel_launch(void* const* d_in, const int* in_sizes, int n_in,
                              void* d_out, int out_size)
{
    const float* x      = (const float*)d_in[0];
    const int*   ei     = (const int*)d_in[1];
    const int*   tgt    = (const int*)d_in[2];
    const int*   batch  = (const int*)d_in[3];
    const float* prot   = (const float*)d_in[4];
    const float* gW1 = (const float*)d_in[5],  *gb1 = (const float*)d_in[6];
    const float* gW2 = (const float*)d_in[7],  *gb2 = (const float*)d_in[8];
    const float* gW3 = (const float*)d_in[9],  *gb3 = (const float*)d_in[10];
    const float* fc1W = (const float*)d_in[11], *fc1b = (const float*)d_in[12];
    const float* fc2W = (const float*)d_in[13], *fc2b = (const float*)d_in[14];
    const float* b1W = (const float*)d_in[15],  *b1b = (const float*)d_in[16];
    const float* b2W = (const float*)d_in[17],  *b2b = (const float*)d_in[18];
    const float* W_b = (const float*)d_in[19];
    const float* W_c = (const float*)d_in[20];
    const float* W_p = (const float*)d_in[21];
    const float* w_hc = (const float*)d_in[22], *w_hp = (const float*)d_in[23];
    const float* c1W = (const float*)d_in[24], *c1b = (const float*)d_in[25];
    const float* c2W = (const float*)d_in[26], *c2b = (const float*)d_in[27];
    const float* oW  = (const float*)d_in[28], *ob  = (const float*)d_in[29];

    const int N = in_sizes[0] / 78;
    const int E = in_sizes[1] / 2;
    const int* src = ei;
    const int* dst = ei + E;

    float* deg   = sym_f(g_deg);
    float* coef  = sym_f(g_coef);
    float* xw    = sym_f(g_xw);
    float* hA    = sym_f(g_hA);
    float* hB    = sym_f(g_hB);
    float* h3    = sym_f(g_h3);
    int*   counts = sym_i(g_counts);
    int*   starts = sym_i(g_starts);
    float* dense = sym_f(g_dense);
    float* fc1o  = sym_f(g_fc1);
    float* hd    = sym_f(g_hd);
    int*   rowmap = sym_i(g_rowmap);
    float* t1    = sym_f(g_t1);
    float* t     = sym_f(g_t);
    float* tbw   = sym_f(g_tbw);
    float* wcomb = sym_f(g_wcomb);
    float* cp    = sym_f(g_cp);
    float* f1    = sym_f(g_f1);
    float* f2    = sym_f(g_f2);
    int* Mdyn  = sym_i(g_Mdyn);
    int* bslot = sym_i(g_bslot);

    static cudaStream_t sB = 0;
    static cudaEvent_t evF = 0, evJ = 0;
    static int tried = 0;
    if (!tried) {
        tried = 1;
        if (cudaStreamCreateWithFlags(&sB, cudaStreamNonBlocking) != cudaSuccess) sB = 0;
        if (sB) {
            if (cudaEventCreateWithFlags(&evF, cudaEventDisableTiming) != cudaSuccess ||
                cudaEventCreateWithFlags(&evJ, cudaEventDisableTiming) != cudaSuccess) {
                sB = 0;
            }
        }
        cudaFuncSetAttribute(coattn_fused, cudaFuncAttributeMaxDynamicSharedMemorySize,
                             SM_FLOATS * 4 + 1024);
    }
    const bool fork = (sB != 0);
    cudaStream_t PS = fork ? sB : (cudaStream_t)0;

    dim3 t16(16, 16);

    // ---- dedup (needed by protein branch) ----
    dedup_fused<<<1, 256>>>(tgt, bslot, rowmap, Mdyn);

    // ---- fork: protein branch ----
    if (fork) { cudaEventRecord(evF, 0); cudaStreamWaitEvent(sB, evF, 0); }
    wcomb_build<<<128, 256, 0, PS>>>(W_b, W_p, wcomb);
    sgemm128<<<dim3(1, TROWS / 128), 256, 0, PS>>>(prot, DPROT, rowmap, b1W, b1b, t1, Mdyn, 128, DPROT, 1, 0, nullptr, nullptr, nullptr);
    sgemm128<<<dim3(1, TROWS / 128), 256, 0, PS>>>(t1, 128, nullptr, b2W, b2b, t, Mdyn, 128, 128, 1, 0, nullptr, nullptr, nullptr);
    sgemm128<<<dim3(2, TROWS / 128), 256, 0, PS>>>(t, 128, nullptr, wcomb, nullptr, tbw, Mdyn, 256, 128, 0, 0, nullptr, nullptr, nullptr);
    if (fork) cudaEventRecord(evJ, sB);

    // ---- main branch ----
    graph_prep<<<1, 1024>>>(src, dst, N, E, deg, coef);
    counts_starts<<<1, 256>>>(batch, N, counts, starts);

    // GCN layer 1 (K=78): dual output xw raw + hA = xw/deg + b
    sgemm64<<<dim3(2, (N + 63) / 64), t16>>>(x, 78, gW1, xw, N, 128, 78, hA, deg, gb1);
    gcn_scatter<<<((long)E * 128 + 255) / 256, 256>>>(src, dst, coef, xw, hA, E, 128);

    // GCN layer 2
    sgemm128<<<dim3(1, N / 128), 256>>>(hA, 128, nullptr, gW2, nullptr, xw, nullptr, 128, 128, 0, 1, hB, deg, gb2);
    gcn_scatter<<<((long)E * 128 + 255) / 256, 256>>>(src, dst, coef, xw, hB, E, 128);

    // GCN layer 3
    sgemm128<<<dim3(2, N / 128), 256>>>(hB, 128, nullptr, gW3, nullptr, xw, nullptr, 256, 128, 0, 1, h3, deg, gb3);
    gcn_scatter<<<((long)E * 256 + 255) / 256, 256>>>(src, dst, coef, xw, h3, E, 256);

    // dense + fc
    dense_build<<<(BGR * MAXN * 64 + 255) / 256, 256>>>(h3, counts, starts, dense);
    const int MD = BGR * MAXN;
    sgemm128<<<dim3(8, MD / 128), 256>>>(dense, 256, nullptr, fc1W, fc1b, fc1o, nullptr, 1024, 256, 1, 0, nullptr, nullptr, nullptr);
    sgemm128<<<dim3(1, MD / 128), 256>>>(fc1o, 1024, nullptr, fc2W, fc2b, hd, nullptr, 128, 1024, 1, 0, nullptr, nullptr, nullptr);

    // ---- join, fused co-attention ----
    if (fork) cudaStreamWaitEvent(0, evJ, 0);
    coattn_fused<<<BGR, 256, SM_FLOATS * 4 + 1024>>>(tbw, t, hd, W_c, w_hc, w_hp, bslot, cp);

    // ---- final MLP ----
    sgemm128<<<dim3(8, 1), 256>>>(cp, 256, nullptr, c1W, c1b, f1, nullptr, 1024, 256, 1, 0, nullptr, nullptr, nullptr);
    sgemm128<<<dim3(4, 1), 256>>>(f1, 1024, nullptr, c2W, c2b, f2, nullptr, 512, 1024, 1, 0, nullptr, nullptr, nullptr);
    out_kernel<<<1, 128>>>(f2, oW, ob, (float*)d_out);
}

// round 7
// speedup vs baseline: 2.8589x; 1.0222x over previous
#include <cuda_runtime.h>
#include <math.h>

// ---------------- problem constants ----------------
#define NNODES 5120
#define NEDGES 20000
#define BGR    128
#define MAXN   45
#define LPROT  512
#define DPROT  1280
#define NPROT  229
#define TROWS  (BGR*LPROT)   // 65536

typedef unsigned long long u64;

// ---------------- f32x2 packed helpers (sm_103a) ----------------
__device__ __forceinline__ void ffma2(u64& d, u64 a, u64 b) {
    asm("fma.rn.f32x2 %0, %1, %2, %0;" : "+l"(d) : "l"(a), "l"(b));
}
__device__ __forceinline__ u64 packdup(float x) {
    u64 r; unsigned u = __float_as_uint(x);
    asm("mov.b64 %0, {%1, %1};" : "=l"(r) : "r"(u));
    return r;
}
__device__ __forceinline__ u64 pack2(float x, float y) {
    u64 r;
    asm("mov.b64 %0, {%1, %2};" : "=l"(r) : "r"(__float_as_uint(x)), "r"(__float_as_uint(y)));
    return r;
}
__device__ __forceinline__ float2 unpack2(u64 v) {
    unsigned lo, hi;
    asm("mov.b64 {%0, %1}, %2;" : "=r"(lo), "=r"(hi) : "l"(v));
    return make_float2(__uint_as_float(lo), __uint_as_float(hi));
}
__device__ __forceinline__ void cp16(unsigned dst, const void* src) {
    asm volatile("cp.async.ca.shared.global [%0], [%1], 16;" :: "r"(dst), "l"(src));
}
__device__ __forceinline__ void cp_commit() {
    asm volatile("cp.async.commit_group;");
}
__device__ __forceinline__ void cp_wait1() {
    asm volatile("cp.async.wait_group 1;");
}

// ---------------- device scratch ----------------
__device__ float g_deg[NNODES];
__device__ float g_coef[NEDGES];
__device__ float g_xw[NNODES*256];
__device__ float g_hA[NNODES*128];
__device__ float g_hB[NNODES*128];
__device__ float g_h3[NNODES*256];
__device__ int   g_counts[BGR];
__device__ int   g_starts[BGR];
__device__ float g_dense[BGR*MAXN*256];
__device__ float g_fc1[BGR*MAXN*1024];
__device__ float g_hd[BGR*MAXN*128];
__device__ int   g_rowmap[TROWS];
__device__ float g_t1[TROWS*128];
__device__ float g_t[TROWS*128];
__device__ float g_tbw[(long)TROWS*256];   // [tb | WptT | pad]
__device__ float g_wcomb[128*256];
__device__ float g_cp[BGR*256];
__device__ float g_f1[BGR*1024];
__device__ float g_f2[BGR*512];
__device__ int g_Mdyn[1];
__device__ int g_bslot[BGR];

// =================================================================
// SGEMM v2: cp.async double-buffered pipeline.
// C = act(relu?(gather(A)) @ B + bias); optional C2 = acc/deg + bias2
// M%128==0 (grid covers), N%128==0, K%16==0, A rows 16B-aligned.
// =================================================================
__global__ __launch_bounds__(256, 2) void sgemm128(
    const float* __restrict__ A, int lda, const int* __restrict__ rowmap,
    const float* __restrict__ B, const float* __restrict__ bias,
    float* __restrict__ C, const int* __restrict__ Mdyn,
    int N, int K, int act, int preRelu,
    float* __restrict__ C2, const float* __restrict__ degv,
    const float* __restrict__ bias2)
{
    __shared__ float As[2][128][20];   // [m][k] row-major, pad 20
    __shared__ float Bs[2][16][132];   // [k][n]
    const int m0 = blockIdx.y * 128;
    if (Mdyn && m0 >= *Mdyn) return;
    const int n0 = blockIdx.x * 128;
    const int tid = threadIdx.x;
    const int tx = tid & 15, ty = tid >> 4;

    u64 acc[8][4];
    #pragma unroll
    for (int i = 0; i < 8; i++)
        #pragma unroll
        for (int j = 0; j < 4; j++) acc[i][j] = 0ULL;

    // A-load descriptors: thread handles chunks tid and tid+256 (of 512 16B chunks)
    const float* asrc[2];
    unsigned adst[2][2];
    #pragma unroll
    for (int i = 0; i < 2; i++) {
        int c = tid + i * 256;
        int m = c >> 2, kq = (c & 3) * 4;
        int row = m0 + m;
        int ar = rowmap ? rowmap[row] : row;
        asrc[i] = A + (long)ar * lda + kq;
        adst[i][0] = (unsigned)__cvta_generic_to_shared(&As[0][m][kq]);
        adst[i][1] = (unsigned)__cvta_generic_to_shared(&As[1][m][kq]);
    }
    // B-load descriptors
    const float* bsrc[2];
    unsigned bdst[2][2];
    #pragma unroll
    for (int i = 0; i < 2; i++) {
        int c = tid + i * 256;
        int kk = c >> 5, n4 = (c & 31) * 4;
        bsrc[i] = B + (long)kk * N + n0 + n4;
        bdst[i][0] = (unsigned)__cvta_generic_to_shared(&Bs[0][kk][n4]);
        bdst[i][1] = (unsigned)__cvta_generic_to_shared(&Bs[1][kk][n4]);
    }

    const int tiles = K >> 4;
    // prologue: issue tile 0 into slot 0
    #pragma unroll
    for (int i = 0; i < 2; i++) { cp16(adst[i][0], asrc[i]); cp16(bdst[i][0], bsrc[i]); }
    cp_commit();

    for (int it = 0; it < tiles; it++) {
        const int slot = it & 1;
        // issue tile it+1 into the other slot (empty commit keeps group count uniform)
        if (it + 1 < tiles) {
            const int kof = (it + 1) << 4;
            const int nslot = slot ^ 1;
            #pragma unroll
            for (int i = 0; i < 2; i++) {
                cp16(adst[i][nslot], asrc[i] + kof);
                cp16(bdst[i][nslot], bsrc[i] + (long)kof * N);
            }
        }
        cp_commit();
        cp_wait1();          // tile `it` complete
        __syncthreads();
        #pragma unroll
        for (int k = 0; k < 16; k++) {
            float av[8];
            #pragma unroll
            for (int r = 0; r < 4; r++) {
                av[r]     = As[slot][ty * 4 + r][k];
                av[r + 4] = As[slot][64 + ty * 4 + r][k];
            }
            if (preRelu) {
                #pragma unroll
                for (int r = 0; r < 8; r++) av[r] = fmaxf(av[r], 0.f);
            }
            float4 b0 = *(const float4*)&Bs[slot][k][tx * 4];
            float4 b1 = *(const float4*)&Bs[slot][k][64 + tx * 4];
            u64 bp[4] = { pack2(b0.x, b0.y), pack2(b0.z, b0.w),
                          pack2(b1.x, b1.y), pack2(b1.z, b1.w) };
            #pragma unroll
            for (int r = 0; r < 8; r++) {
                u64 ap = packdup(av[r]);
                #pragma unroll
                for (int j = 0; j < 4; j++) ffma2(acc[r][j], ap, bp[j]);
            }
        }
        __syncthreads();     // slot consumed; next iteration may overwrite it
    }

    #pragma unroll
    for (int r = 0; r < 8; r++) {
        int gm = m0 + ((r < 4) ? (ty * 4 + r) : (64 + ty * 4 + r - 4));
        #pragma unroll
        for (int j = 0; j < 4; j++) {
            int gn = n0 + ((j < 2) ? (tx * 4 + j * 2) : (64 + tx * 4 + (j - 2) * 2));
            float2 v = unpack2(acc[r][j]);
            if (C2) {
                float dg = degv[gm];
                float2 w = make_float2(v.x / dg + bias2[gn], v.y / dg + bias2[gn + 1]);
                *(float2*)&C2[(long)gm * N + gn] = w;
            }
            if (bias) { v.x += bias[gn]; v.y += bias[gn + 1]; }
            if (act == 1) { v.x = fmaxf(v.x, 0.f); v.y = fmaxf(v.y, 0.f); }
            else if (act == 2) { v.x = tanhf(v.x); v.y = tanhf(v.y); }
            *(float2*)&C[(long)gm * N + gn] = v;
        }
    }
}

// ---------------- generic SGEMM (GCN layer 1, K=78) ----------------
__global__ __launch_bounds__(256) void sgemm64(
    const float* __restrict__ A, int lda,
    const float* __restrict__ B, float* __restrict__ C,
    int M, int N, int K,
    float* __restrict__ C2, const float* __restrict__ degv,
    const float* __restrict__ bias2)
{
    __shared__ float As[16][64];
    __shared__ float Bs[16][68];
    const int tid = threadIdx.y * 16 + threadIdx.x;
    const int m0 = blockIdx.y * 64;
    const int n0 = blockIdx.x * 64;
    float acc[4][4] = {};
    for (int kt = 0; kt < K; kt += 16) {
        #pragma unroll
        for (int i = tid; i < 64 * 16; i += 256) {
            int m = i >> 4, kk = i & 15;
            int gm = m0 + m, gk = kt + kk;
            float v = 0.f;
            if (gm < M && gk < K) v = A[(long)gm * lda + gk];
            As[kk][m] = v;
        }
        #pragma unroll
        for (int i = tid; i < 16 * 64; i += 256) {
            int kk = i >> 6, n = i & 63;
            int gk = kt + kk, gn = n0 + n;
            Bs[kk][n] = (gk < K && gn < N) ? B[(long)gk * N + gn] : 0.f;
        }
        __syncthreads();
        #pragma unroll
        for (int kk = 0; kk < 16; kk++) {
            float a[4];
            #pragma unroll
            for (int i = 0; i < 4; i++) a[i] = As[kk][threadIdx.y * 4 + i];
            float4 b4 = *(const float4*)&Bs[kk][threadIdx.x * 4];
            float bv[4] = { b4.x, b4.y, b4.z, b4.w };
            #pragma unroll
            for (int i = 0; i < 4; i++)
                #pragma unroll
                for (int j = 0; j < 4; j++) acc[i][j] += a[i] * bv[j];
        }
        __syncthreads();
    }
    #pragma unroll
    for (int i = 0; i < 4; i++) {
        int gm = m0 + threadIdx.y * 4 + i;
        if (gm >= M) continue;
        #pragma unroll
        for (int j = 0; j < 4; j++) {
            int gn = n0 + threadIdx.x * 4 + j;
            if (gn >= N) continue;
            float v = acc[i][j];
            if (C2) C2[(long)gm * N + gn] = v / degv[gm] + bias2[gn];
            C[(long)gm * N + gn] = v;
        }
    }
}

// ---------------- prep_all: dedup + graph deg/coef + batch counts ----------------
__global__ __launch_bounds__(1024) void prep_all(
    const int* __restrict__ tgt, const int* __restrict__ src,
    const int* __restrict__ dst, const int* __restrict__ batch,
    int n, int E,
    int* bslot, int* rowmap, int* Mdyn,
    float* deg, float* coef, int* counts, int* starts)
{
    __shared__ float sdeg[NNODES];
    __shared__ int flag[NPROT];
    __shared__ int slot[NPROT];
    __shared__ int uniq[BGR];
    __shared__ int cbin[BGR];
    __shared__ int nu_s;
    const int tid = threadIdx.x;

    // init
    for (int i = tid; i < n; i += 1024) sdeg[i] = 1.0f;
    if (tid < NPROT) flag[tid] = 0;
    if (tid < BGR) cbin[tid] = 0;
    __syncthreads();
    // counts + deg accumulation + dedup flags
    if (tid < BGR) flag[tgt[tid]] = 1;
    for (int e = tid; e < E; e += 1024) atomicAdd(&sdeg[dst[e]], 1.0f);
    for (int i = tid; i < n; i += 1024) atomicAdd(&cbin[batch[i]], 1);
    __syncthreads();
    // serial scans
    if (tid == 0) {
        int s = 0;
        for (int p = 0; p < NPROT; p++) {
            if (flag[p]) { slot[p] = s; uniq[s] = p; s++; }
            else slot[p] = -1;
        }
        nu_s = s;
        Mdyn[0] = s * LPROT;
    } else if (tid == 32) {
        int s = 0;
        for (int b = 0; b < BGR; b++) { starts[b] = s; counts[b] = cbin[b]; s += cbin[b]; }
    }
    __syncthreads();
    // outputs
    if (tid < BGR) bslot[tid] = slot[tgt[tid]];
    for (int i = tid; i < n; i += 1024) deg[i] = sdeg[i];
    for (int e = tid; e < E; e += 1024)
        coef[e] = rsqrtf(sdeg[src[e]]) * rsqrtf(sdeg[dst[e]]);
    int nu = nu_s;
    for (int r = tid; r < TROWS; r += 1024) {
        int s = r >> 9;
        rowmap[r] = (s < nu) ? (uniq[s] * LPROT + (r & (LPROT - 1))) : 0;
    }
}

// ---------------- GCN scatter (float4 per thread) ----------------
__global__ void gcn_scatter4(const int* __restrict__ src, const int* __restrict__ dst,
                             const float* __restrict__ coef, const float* __restrict__ xw,
                             float* out, int E, int F4) {
    long i = (long)blockIdx.x * blockDim.x + threadIdx.x;
    if (i >= (long)E * F4) return;
    int e = (int)(i / F4);
    int f = (int)(i - (long)e * F4) * 4;
    float c = coef[e];
    int s = src[e], d = dst[e];
    const int F = F4 * 4;
    float4 v = *(const float4*)&xw[(long)s * F + f];
    float* o = &out[(long)d * F + f];
    atomicAdd(o + 0, v.x * c);
    atomicAdd(o + 1, v.y * c);
    atomicAdd(o + 2, v.z * c);
    atomicAdd(o + 3, v.w * c);
}

// ---------------- to_dense_batch gather ----------------
__global__ void dense_build(const float* __restrict__ h3,
                            const int* __restrict__ counts,
                            const int* __restrict__ starts,
                            float* __restrict__ dense) {
    int i = blockIdx.x * blockDim.x + threadIdx.x;
    if (i >= BGR * MAXN * 64) return;
    int b = i / (MAXN * 64);
    int rem = i - b * (MAXN * 64);
    int pos = rem >> 6, f4 = rem & 63;
    float4 v = make_float4(0.f, 0.f, 0.f, 0.f);
    if (pos < counts[b]) {
        v = ((const float4*)(h3 + (long)(starts[b] + pos) * 256))[f4];
        v.x = fmaxf(v.x, 0.f); v.y = fmaxf(v.y, 0.f);
        v.z = fmaxf(v.z, 0.f); v.w = fmaxf(v.w, 0.f);
    }
    ((float4*)dense)[i] = v;
}

// ---------------- Wcomb = [W_b | W_p^T | 0]  [128,256] ----------------
__global__ void wcomb_build(const float* __restrict__ Wb, const float* __restrict__ Wp,
                            float* __restrict__ Wc) {
    int i = blockIdx.x * 256 + threadIdx.x;
    if (i >= 128 * 256) return;
    int k = i >> 8, n = i & 255;
    float v = 0.f;
    if (n < 128) v = Wb[k * 128 + n];
    else if (n < 160) v = Wp[(n - 128) * 128 + k];
    Wc[i] = v;
}

// =================================================================
// FUSED CO-ATTENTION (unchanged from R6)
// =================================================================
#define PHD 132
#define OFF_HD   0
#define OFF_WCX  (OFF_HD + 45*PHD)
#define OFF_C    (OFF_WCX + 32*48)
#define OFF_TB   (OFF_C + 64*48)
#define OFF_AP   (OFF_TB + 64*PHD)
#define OFF_AC   (OFF_AP + 512)
#define OFF_RED  (OFF_AC + 48)
#define OFF_WC   (OFF_RED + 256)
#define OFF_WP   (OFF_WC + 32)
#define OFF_SCAL (OFF_WP + 32)
#define SM_FLOATS (OFF_SCAL + 4)

__global__ __launch_bounds__(256) void coattn_fused(
    const float* __restrict__ tbw, const float* __restrict__ t,
    const float* __restrict__ hd, const float* __restrict__ Wc_g,
    const float* __restrict__ whc, const float* __restrict__ whp,
    const int* __restrict__ bslot, float* __restrict__ cp)
{
    extern __shared__ float sm[];
    float* s_hd  = sm + OFF_HD;
    float* s_wcx = sm + OFF_WCX;
    float* s_C   = sm + OFF_C;
    float* s_tb  = sm + OFF_TB;
    float* s_ap  = sm + OFF_AP;
    float* s_ac  = sm + OFF_AC;
    float* s_red = sm + OFF_RED;
    float* s_wc  = sm + OFF_WC;
    float* s_wp  = sm + OFF_WP;
    float* s_scal= sm + OFF_SCAL;

    const int b = blockIdx.x;
    const int tid = threadIdx.x;
    const long base = (long)bslot[b] * LPROT;
    const float* hd_b = hd + (long)b * MAXN * 128;

    for (int idx = tid; idx < MAXN * 32; idx += 256) {
        int s = idx >> 5, v4 = (idx & 31) * 4;
        *(float4*)&s_hd[s * PHD + v4] = *(const float4*)&hd_b[s * 128 + v4];
    }
    if (tid < 32) { s_wc[tid] = whc[tid]; s_wp[tid] = whp[tid]; }
    if (tid < 48) s_ac[tid] = 0.f;
    __syncthreads();

    for (int idx = tid; idx < 32 * MAXN; idx += 256) {
        int k = idx / MAXN, s = idx - k * MAXN;
        float acc = 0.f;
        #pragma unroll
        for (int kk = 0; kk < 32; kk++) {
            float4 a = *(const float4*)&Wc_g[k * 128 + kk * 4];
            float4 h4 = *(const float4*)&s_hd[s * PHD + kk * 4];
            acc += a.x * h4.x + a.y * h4.y + a.z * h4.z + a.w * h4.w;
        }
        s_wcx[k * 48 + s] = acc;
    }

    const int kt2 = (tid / 15) * 2;
    const int st3 = (tid % 15) * 3;
    float hc00 = 0.f, hc01 = 0.f, hc02 = 0.f, hc10 = 0.f, hc11 = 0.f, hc12 = 0.f;

    for (int cc = 0; cc < 8; cc++) {
        const int lbase = cc * 64;
        __syncthreads();
        for (int idx = tid; idx < 64 * 32; idx += 256) {
            int l = idx >> 5, v4 = (idx & 31) * 4;
            *(float4*)&s_tb[l * PHD + v4] =
                *(const float4*)&tbw[(base + lbase + l) * 256 + v4];
        }
        __syncthreads();
        if (tid < 240) {
            int lt = (tid / 15) * 4;
            float ca[4][3] = {};
            #pragma unroll 8
            for (int kk = 0; kk < 32; kk++) {
                float4 a0 = *(const float4*)&s_tb[(lt + 0) * PHD + kk * 4];
                float4 a1 = *(const float4*)&s_tb[(lt + 1) * PHD + kk * 4];
                float4 a2 = *(const float4*)&s_tb[(lt + 2) * PHD + kk * 4];
                float4 a3 = *(const float4*)&s_tb[(lt + 3) * PHD + kk * 4];
                float4 h0 = *(const float4*)&s_hd[(st3 + 0) * PHD + kk * 4];
                float4 h1 = *(const float4*)&s_hd[(st3 + 1) * PHD + kk * 4];
                float4 h2 = *(const float4*)&s_hd[(st3 + 2) * PHD + kk * 4];
                ca[0][0] += a0.x*h0.x + a0.y*h0.y + a0.z*h0.z + a0.w*h0.w;
                ca[0][1] += a0.x*h1.x + a0.y*h1.y + a0.z*h1.z + a0.w*h1.w;
                ca[0][2] += a0.x*h2.x + a0.y*h2.y + a0.z*h2.z + a0.w*h2.w;
                ca[1][0] += a1.x*h0.x + a1.y*h0.y + a1.z*h0.z + a1.w*h0.w;
                ca[1][1] += a1.x*h1.x + a1.y*h1.y + a1.z*h1.z + a1.w*h1.w;
                ca[1][2] += a1.x*h2.x + a1.y*h2.y + a1.z*h2.z + a1.w*h2.w;
                ca[2][0] += a2.x*h0.x + a2.y*h0.y + a2.z*h0.z + a2.w*h0.w;
                ca[2][1] += a2.x*h1.x + a2.y*h1.y + a2.z*h1.z + a2.w*h1.w;
                ca[2][2] += a2.x*h2.x + a2.y*h2.y + a2.z*h2.z + a2.w*h2.w;
                ca[3][0] += a3.x*h0.x + a3.y*h0.y + a3.z*h0.z + a3.w*h0.w;
                ca[3][1] += a3.x*h1.x + a3.y*h1.y + a3.z*h1.z + a3.w*h1.w;
                ca[3][2] += a3.x*h2.x + a3.y*h2.y + a3.z*h2.z + a3.w*h2.w;
            }
            #pragma unroll
            for (int i = 0; i < 4; i++)
                #pragma unroll
                for (int j = 0; j < 3; j++)
                    s_C[(lt + i) * 48 + st3 + j] = tanhf(ca[i][j]);
        }
        __syncthreads();
        if (tid < 240) {
            for (int l = 0; l < 64; l++) {
                const float* wrow = &tbw[(base + lbase + l) * 256 + 128];
                float w0 = wrow[kt2], w1 = wrow[kt2 + 1];
                float c0 = s_C[l * 48 + st3];
                float c1 = s_C[l * 48 + st3 + 1];
                float c2 = s_C[l * 48 + st3 + 2];
                hc00 += w0 * c0; hc01 += w0 * c1; hc02 += w0 * c2;
                hc10 += w1 * c0; hc11 += w1 * c1; hc12 += w1 * c2;
            }
        }
        {
            int l = tid >> 2, q = tid & 3;
            float cl[45];
            #pragma unroll
            for (int s = 0; s < 45; s++) cl[s] = s_C[l * 48 + s];
            const float* wrow = &tbw[(base + lbase + l) * 256 + 128];
            float part = 0.f;
            #pragma unroll
            for (int i = 0; i < 8; i++) {
                int k = q * 8 + i;
                float v = wrow[k];
                const float* wx = &s_wcx[k * 48];
                #pragma unroll
                for (int s = 0; s < 45; s++) v += wx[s] * cl[s];
                part += s_wp[k] * tanhf(v);
            }
            part += __shfl_down_sync(0xffffffffu, part, 2);
            part += __shfl_down_sync(0xffffffffu, part, 1);
            if (q == 0) s_ap[lbase + l] = part;
        }
    }
    __syncthreads();

    if (tid < 240) {
        float h;
        h = tanhf(s_wcx[kt2 * 48 + st3] + hc00);       atomicAdd(&s_ac[st3],     s_wc[kt2] * h);
        h = tanhf(s_wcx[kt2 * 48 + st3 + 1] + hc01);   atomicAdd(&s_ac[st3 + 1], s_wc[kt2] * h);
        h = tanhf(s_wcx[kt2 * 48 + st3 + 2] + hc02);   atomicAdd(&s_ac[st3 + 2], s_wc[kt2] * h);
        h = tanhf(s_wcx[(kt2+1) * 48 + st3] + hc10);     atomicAdd(&s_ac[st3],     s_wc[kt2+1] * h);
        h = tanhf(s_wcx[(kt2+1) * 48 + st3 + 1] + hc11); atomicAdd(&s_ac[st3 + 1], s_wc[kt2+1] * h);
        h = tanhf(s_wcx[(kt2+1) * 48 + st3 + 2] + hc12); atomicAdd(&s_ac[st3 + 2], s_wc[kt2+1] * h);
    }
    __syncthreads();

    float m1 = fmaxf(s_ap[tid], s_ap[tid + 256]);
    s_red[tid] = m1; __syncthreads();
    for (int o = 128; o > 0; o >>= 1) {
        if (tid < o) s_red[tid] = fmaxf(s_red[tid], s_red[tid + o]);
        __syncthreads();
    }
    float mx = s_red[0]; __syncthreads();
    float e1 = expf(s_ap[tid] - mx), e2 = expf(s_ap[tid + 256] - mx);
    s_ap[tid] = e1; s_ap[tid + 256] = e2;
    s_red[tid] = e1 + e2; __syncthreads();
    for (int o = 128; o > 0; o >>= 1) {
        if (tid < o) s_red[tid] += s_red[tid + o];
        __syncthreads();
    }
    if (tid == 0) s_scal[0] = 1.f / s_red[0];
    if (tid == 0) {
        float amx = -1e30f;
        for (int s = 0; s < MAXN; s++) amx = fmaxf(amx, s_ac[s]);
        float sum = 0.f;
        for (int s = 0; s < MAXN; s++) { float e = expf(s_ac[s] - amx); s_ac[s] = e; sum += e; }
        float inv = 1.f / sum;
        for (int s = 0; s < MAXN; s++) s_ac[s] *= inv;
    }
    __syncthreads();

    {
        int h = tid >> 7, m = tid & 127;
        float accp = 0.f;
        int l0 = h * 256;
        for (int l = 0; l < 256; l++)
            accp += s_ap[l0 + l] * t[(base + l0 + l) * 128 + m];
        s_red[tid] = accp;
        __syncthreads();
        if (h == 0) {
            float accc = 0.f;
            #pragma unroll
            for (int s = 0; s < MAXN; s++) accc += s_ac[s] * s_hd[s * PHD + m];
            cp[b * 256 + m] = accc;
            cp[b * 256 + 128 + m] = (s_red[m] + s_red[128 + m]) * s_scal[0];
        }
    }
}

// ---------------- final output ----------------
__global__ void out_kernel(const float* __restrict__ f2, const float* __restrict__ oW,
                           const float* __restrict__ ob, float* __restrict__ out) {
    int b = threadIdx.x;
    if (b < BGR) {
        float s = 0.f;
        for (int j = 0; j < 512; j += 4) {
            float4 a = *(const float4*)&f2[b * 512 + j];
            float4 w = *(const float4*)&oW[j];
            s += a.x * w.x + a.y * w.y + a.z * w.z + a.w * w.w;
        }
        out[b] = s + ob[0];
    }
}

// ---------------- host launcher ----------------
static float* sym_f(const void* s) { void* p = nullptr; cudaGetSymbolAddress(&p, s); return (float*)p; }
static int*   sym_i(const void* s) { void* p = nullptr; cudaGetSymbolAddress(&p, s); return (int*)p; }

extern "C" void kernel_launch(void* const* d_in, const int* in_sizes, int n_in,
                              void* d_out, int out_size)
{
    const float* x      = (const float*)d_in[0];
    const int*   ei     = (const int*)d_in[1];
    const int*   tgt    = (const int*)d_in[2];
    const int*   batch  = (const int*)d_in[3];
    const float* prot   = (const float*)d_in[4];
    const float* gW1 = (const float*)d_in[5],  *gb1 = (const float*)d_in[6];
    const float* gW2 = (const float*)d_in[7],  *gb2 = (const float*)d_in[8];
    const float* gW3 = (const float*)d_in[9],  *gb3 = (const float*)d_in[10];
    const float* fc1W = (const float*)d_in[11], *fc1b = (const float*)d_in[12];
    const float* fc2W = (const float*)d_in[13], *fc2b = (const float*)d_in[14];
    const float* b1W = (const float*)d_in[15],  *b1b = (const float*)d_in[16];
    const float* b2W = (const float*)d_in[17],  *b2b = (const float*)d_in[18];
    const float* W_b = (const float*)d_in[19];
    const float* W_c = (const float*)d_in[20];
    const float* W_p = (const float*)d_in[21];
    const float* w_hc = (const float*)d_in[22], *w_hp = (const float*)d_in[23];
    const float* c1W = (const float*)d_in[24], *c1b = (const float*)d_in[25];
    const float* c2W = (const float*)d_in[26], *c2b = (const float*)d_in[27];
    const float* oW  = (const float*)d_in[28], *ob  = (const float*)d_in[29];

    const int N = in_sizes[0] / 78;
    const int E = in_sizes[1] / 2;
    const int* src = ei;
    const int* dst = ei + E;

    float* deg   = sym_f(g_deg);
    float* coef  = sym_f(g_coef);
    float* xw    = sym_f(g_xw);
    float* hA    = sym_f(g_hA);
    float* hB    = sym_f(g_hB);
    float* h3    = sym_f(g_h3);
    int*   counts = sym_i(g_counts);
    int*   starts = sym_i(g_starts);
    float* dense = sym_f(g_dense);
    float* fc1o  = sym_f(g_fc1);
    float* hd    = sym_f(g_hd);
    int*   rowmap = sym_i(g_rowmap);
    float* t1    = sym_f(g_t1);
    float* t     = sym_f(g_t);
    float* tbw   = sym_f(g_tbw);
    float* wcomb = sym_f(g_wcomb);
    float* cp    = sym_f(g_cp);
    float* f1    = sym_f(g_f1);
    float* f2    = sym_f(g_f2);
    int* Mdyn  = sym_i(g_Mdyn);
    int* bslot = sym_i(g_bslot);

    static cudaStream_t sB = 0;
    static cudaEvent_t evF = 0, evJ = 0;
    static int tried = 0;
    if (!tried) {
        tried = 1;
        if (cudaStreamCreateWithFlags(&sB, cudaStreamNonBlocking) != cudaSuccess) sB = 0;
        if (sB) {
            if (cudaEventCreateWithFlags(&evF, cudaEventDisableTiming) != cudaSuccess ||
                cudaEventCreateWithFlags(&evJ, cudaEventDisableTiming) != cudaSuccess) {
                sB = 0;
            }
        }
        cudaFuncSetAttribute(coattn_fused, cudaFuncAttributeMaxDynamicSharedMemorySize,
                             SM_FLOATS * 4 + 1024);
    }
    const bool fork = (sB != 0);
    cudaStream_t PS = fork ? sB : (cudaStream_t)0;

    dim3 t16(16, 16);

    // ---- fused prep: dedup + graph deg/coef + batch counts ----
    prep_all<<<1, 1024>>>(tgt, src, dst, batch, N, E,
                          bslot, rowmap, Mdyn, deg, coef, counts, starts);

    // ---- fork: protein branch ----
    if (fork) { cudaEventRecord(evF, 0); cudaStreamWaitEvent(sB, evF, 0); }
    wcomb_build<<<128, 256, 0, PS>>>(W_b, W_p, wcomb);
    sgemm128<<<dim3(1, TROWS / 128), 256, 0, PS>>>(prot, DPROT, rowmap, b1W, b1b, t1, Mdyn, 128, DPROT, 1, 0, nullptr, nullptr, nullptr);
    sgemm128<<<dim3(1, TROWS / 128), 256, 0, PS>>>(t1, 128, nullptr, b2W, b2b, t, Mdyn, 128, 128, 1, 0, nullptr, nullptr, nullptr);
    sgemm128<<<dim3(2, TROWS / 128), 256, 0, PS>>>(t, 128, nullptr, wcomb, nullptr, tbw, Mdyn, 256, 128, 0, 0, nullptr, nullptr, nullptr);
    if (fork) cudaEventRecord(evJ, sB);

    // ---- main branch: GCN stack ----
    sgemm64<<<dim3(2, (N + 63) / 64), t16>>>(x, 78, gW1, xw, N, 128, 78, hA, deg, gb1);
    gcn_scatter4<<<((long)E * 32 + 255) / 256, 256>>>(src, dst, coef, xw, hA, E, 32);

    sgemm128<<<dim3(1, N / 128), 256>>>(hA, 128, nullptr, gW2, nullptr, xw, nullptr, 128, 128, 0, 1, hB, deg, gb2);
    gcn_scatter4<<<((long)E * 32 + 255) / 256, 256>>>(src, dst, coef, xw, hB, E, 32);

    sgemm128<<<dim3(2, N / 128), 256>>>(hB, 128, nullptr, gW3, nullptr, xw, nullptr, 256, 128, 0, 1, h3, deg, gb3);
    gcn_scatter4<<<((long)E * 64 + 255) / 256, 256>>>(src, dst, coef, xw, h3, E, 64);

    dense_build<<<(BGR * MAXN * 64 + 255) / 256, 256>>>(h3, counts, starts, dense);
    const int MD = BGR * MAXN;
    sgemm128<<<dim3(8, MD / 128), 256>>>(dense, 256, nullptr, fc1W, fc1b, fc1o, nullptr, 1024, 256, 1, 0, nullptr, nullptr, nullptr);
    sgemm128<<<dim3(1, MD / 128), 256>>>(fc1o, 1024, nullptr, fc2W, fc2b, hd, nullptr, 128, 1024, 1, 0, nullptr, nullptr, nullptr);

    // ---- join, fused co-attention ----
    if (fork) cudaStreamWaitEvent(0, evJ, 0);
    coattn_fused<<<BGR, 256, SM_FLOATS * 4 + 1024>>>(tbw, t, hd, W_c, w_hc, w_hp, bslot, cp);

    // ---- final MLP ----
    sgemm128<<<dim3(8, 1), 256>>>(cp, 256, nullptr, c1W, c1b, f1, nullptr, 1024, 256, 1, 0, nullptr, nullptr, nullptr);
    sgemm128<<<dim3(4, 1), 256>>>(f1, 1024, nullptr, c2W, c2b, f2, nullptr, 512, 1024, 1, 0, nullptr, nullptr, nullptr);
    out_kernel<<<1, 128>>>(f2, oW, ob, (float*)d_out);
}